// round 13
// baseline (speedup 1.0000x reference)
#include <cuda_runtime.h>
#include <cuda_bf16.h>
#include <cstdint>
#include <cstddef>

#define SEQ    4096
#define HID    2048
#define HEADS  16
#define HD     128
#define NB     64
#define SCALE  0.08838834764831845f   // 1/sqrt(128)

#define GM 4096
#define GN 2048
#define GK 2048

// ---------------- scratch planes (device globals; no allocation allowed) ----
__device__ __nv_bfloat16 g_ah[SEQ * HID], g_al[SEQ * HID];   // activations
__device__ __nv_bfloat16 g_qh[SEQ * HID], g_ql[SEQ * HID];
__device__ __nv_bfloat16 g_kh[SEQ * HID], g_kl[SEQ * HID];
__device__ __nv_bfloat16 g_vh[SEQ * HID], g_vl[SEQ * HID];
__device__ __nv_bfloat16 g_oh[SEQ * HID], g_ol[SEQ * HID];   // attn output
__device__ __nv_bfloat16 g_wqh[HID * HID], g_wql[HID * HID];
__device__ __nv_bfloat16 g_wkh[HID * HID], g_wkl[HID * HID];
__device__ __nv_bfloat16 g_wvh[HID * HID], g_wvl[HID * HID];
__device__ __nv_bfloat16 g_woh[HID * HID], g_wol[HID * HID];

// =================== baseline-PTX helpers (sm_80+ ISA only) =================
__device__ __forceinline__ uint32_t smem_u32(const void* p) {
    uint32_t a;
    asm("{ .reg .u64 t; cvta.to.shared.u64 t, %1; cvt.u32.u64 %0, t; }" : "=r"(a) : "l"(p));
    return a;
}
__device__ __forceinline__ void cpasync16(uint32_t dst, const void* src) {
    asm volatile("cp.async.cg.shared.global [%0], [%1], 16;" :: "r"(dst), "l"(src));
}
#define CP_COMMIT() asm volatile("cp.async.commit_group;" ::: "memory")
#define CP_WAIT1()  asm volatile("cp.async.wait_group 1;" ::: "memory")
#define CP_WAIT0()  asm volatile("cp.async.wait_group 0;" ::: "memory")

#define LDSM_X4(r0, r1, r2, r3, addr) \
    asm volatile("ldmatrix.sync.aligned.m8n8.x4.shared.b16 {%0,%1,%2,%3}, [%4];" \
                 : "=r"(r0), "=r"(r1), "=r"(r2), "=r"(r3) : "r"(addr))
#define LDSM_X4_T(r0, r1, r2, r3, addr) \
    asm volatile("ldmatrix.sync.aligned.m8n8.x4.trans.shared.b16 {%0,%1,%2,%3}, [%4];" \
                 : "=r"(r0), "=r"(r1), "=r"(r2), "=r"(r3) : "r"(addr))

__device__ __forceinline__ void mma16816(float* d, const uint32_t* a, const uint32_t* b) {
    asm volatile("mma.sync.aligned.m16n8k16.row.col.f32.bf16.bf16.f32 "
                 "{%0,%1,%2,%3}, {%4,%5,%6,%7}, {%8,%9}, {%0,%1,%2,%3};"
                 : "+f"(d[0]), "+f"(d[1]), "+f"(d[2]), "+f"(d[3])
                 : "r"(a[0]), "r"(a[1]), "r"(a[2]), "r"(a[3]), "r"(b[0]), "r"(b[1]));
}

__device__ __forceinline__ uint32_t bf2bits(__nv_bfloat162 v) {
    return *reinterpret_cast<uint32_t*>(&v);
}
__device__ __forceinline__ void pack_hilo(float x, float y, uint32_t& hi, uint32_t& lo) {
    __nv_bfloat162 h = __floats2bfloat162_rn(x, y);
    float2 f = __bfloat1622float2(h);
    __nv_bfloat162 l = __floats2bfloat162_rn(x - f.x, y - f.y);
    hi = bf2bits(h); lo = bf2bits(l);
}

// =================== fused fp32 -> bf16 hi/lo split =========================
#define REG4 (1u << 20)

__global__ __launch_bounds__(256) void split_all(
    const float* __restrict__ x,  const float* __restrict__ wq,
    const float* __restrict__ wk, const float* __restrict__ wv,
    const float* __restrict__ wo)
{
    const int r = blockIdx.y;
    const float* src;
    __nv_bfloat16 *hi, *lo;
    size_t off = 0;
    if (r < 2)       { src = x;  hi = g_ah;  lo = g_al;  off = (size_t)r * REG4; }
    else if (r == 2) { src = wq; hi = g_wqh; lo = g_wql; }
    else if (r == 3) { src = wk; hi = g_wkh; lo = g_wkl; }
    else if (r == 4) { src = wv; hi = g_wvh; lo = g_wvl; }
    else             { src = wo; hi = g_woh; lo = g_wol; }

    const size_t i = off + (size_t)blockIdx.x * 256 + threadIdx.x;
    float4 v = reinterpret_cast<const float4*>(src)[i];
    uint32_t h01, l01, h23, l23;
    pack_hilo(v.x, v.y, h01, l01);
    pack_hilo(v.z, v.w, h23, l23);
    reinterpret_cast<uint2*>(hi)[i] = make_uint2(h01, h23);
    reinterpret_cast<uint2*>(lo)[i] = make_uint2(l01, l23);
}

// =================== bf16x3 GEMM core (mma.sync, 128x32 CTA, 4 CTA/SM) ======
// Warp tile 32x16 (4m x 2n warps). 2-stage cp.async (20KB/stage, 40KB total),
// single sync per k-tile. __launch_bounds__(256,4) caps regs at 64
// -> 4 CTAs/SM (32 warps, 8/SMSP).
#define KTILE 32
#define NT (GK / KTILE)
#define ROWB 64
#define APLANE 8192                  // A: 128 rows * 64B
#define BPLANE 2048                  // B:  32 rows * 64B
#define STAGEB (2 * APLANE + 2 * BPLANE)   // 20 KB
#define GEMM_SMEM (2 * STAGEB)             // 40 KB
#define SWZ(r, c) ((uint32_t)((r) * ROWB + (((c) ^ (((r) >> 1) & 3)) * 16)))

template<bool SPLIT_OUT>
__device__ __forceinline__ void gemm_core(
    const __nv_bfloat16* __restrict__ Ah, const __nv_bfloat16* __restrict__ Al,
    const __nv_bfloat16* __restrict__ Bh, const __nv_bfloat16* __restrict__ Bl,
    float* __restrict__ C, __nv_bfloat16* __restrict__ Ch, __nv_bfloat16* __restrict__ Cl)
{
    extern __shared__ char smem[];
    const uint32_t sb = smem_u32(smem);
    const int tid  = threadIdx.x;
    const int lane = tid & 31;
    const int w    = tid >> 5;
    const int bm   = blockIdx.y * 128;
    const int bn   = blockIdx.x * 32;

    // A loads: thread -> row tid/2 (0..127), chunk pair (tid&1)*2, both planes
    const int lr  = tid >> 1;
    const int lc0 = (tid & 1) << 1;
    const __nv_bfloat16* gAh = Ah + (size_t)(bm + lr) * GK + lc0 * 8;
    const __nv_bfloat16* gAl = Al + (size_t)(bm + lr) * GK + lc0 * 8;
    const uint32_t sA0 = SWZ(lr, lc0), sA1 = SWZ(lr, lc0 + 1);
    // B loads: threads 0-127 -> Bh, 128-255 -> Bl; row (tid&127)/4, chunk tid&3
    const int plB = tid >> 7;
    const int rbB = (tid & 127) >> 2;
    const int cbB = tid & 3;
    const __nv_bfloat16* gB =
        (plB ? Bl : Bh) + (size_t)(bn + rbB) * GK + cbB * 8;
    const uint32_t sBoff = 2 * APLANE + plB * BPLANE + SWZ(rbB, cbB);

    auto load_stage = [&](int t, int st) {
        const uint32_t base = sb + st * STAGEB;
        const int ko = t * KTILE;
        cpasync16(base + sA0, gAh + ko);
        cpasync16(base + sA1, gAh + ko + 8);
        cpasync16(base + APLANE + sA0, gAl + ko);
        cpasync16(base + APLANE + sA1, gAl + ko + 8);
        cpasync16(base + sBoff, gB + ko);
    };

    const int m0 = (w & 3) * 32;     // 4 warps over M
    const int n0 = (w >> 2) * 16;    // 2 warps over N

    // A-operand x4 lane map
    const int xrA = ((lane >> 3) & 1) * 8 + (lane & 7);
    const int xcA = (lane >> 4) & 1;
    // B-operand x4 lane map: regs -> [t0.klo, t0.khi, t1.klo, t1.khi]
    const int xrB = ((lane >> 4) & 1) * 8 + (lane & 7);
    const int xcB = (lane >> 3) & 1;

    float acc[4][4];
#pragma unroll
    for (int i = 0; i < 4; i++)
#pragma unroll
        for (int j = 0; j < 4; j++) acc[i][j] = 0.f;

    load_stage(0, 0);
    CP_COMMIT();

    for (int t = 0; t < NT; t++) {
        CP_WAIT0();          // tile t's group complete
        __syncthreads();     // every warp done computing tile t-1; tile t visible

        if (t + 1 < NT) {
            load_stage(t + 1, (t + 1) & 1);
            CP_COMMIT();     // fetches during compute of tile t
        }

        const uint32_t stage = sb + (t & 1) * STAGEB;
#pragma unroll
        for (int ks = 0; ks < 2; ks++) {
            uint32_t ah4[2][4], al4[2][4];
#pragma unroll
            for (int fm = 0; fm < 2; fm++) {
                const uint32_t sw = SWZ(m0 + fm * 16 + xrA, 2 * ks + xcA);
                LDSM_X4(ah4[fm][0], ah4[fm][1], ah4[fm][2], ah4[fm][3], stage + sw);
                LDSM_X4(al4[fm][0], al4[fm][1], al4[fm][2], al4[fm][3], stage + APLANE + sw);
            }
            uint32_t bh4[4], bl4[4];
            {
                const uint32_t sw = SWZ(n0 + xrB, 2 * ks + xcB);
                LDSM_X4(bh4[0], bh4[1], bh4[2], bh4[3], stage + 2 * APLANE + sw);
                LDSM_X4(bl4[0], bl4[1], bl4[2], bl4[3], stage + 2 * APLANE + BPLANE + sw);
            }
            // combo 1: Ah * Bh
#pragma unroll
            for (int fm = 0; fm < 2; fm++) {
                mma16816(acc[fm * 2 + 0], ah4[fm], bh4 + 0);
                mma16816(acc[fm * 2 + 1], ah4[fm], bh4 + 2);
            }
            // combo 2: Ah * Bl
#pragma unroll
            for (int fm = 0; fm < 2; fm++) {
                mma16816(acc[fm * 2 + 0], ah4[fm], bl4 + 0);
                mma16816(acc[fm * 2 + 1], ah4[fm], bl4 + 2);
            }
            // combo 3: Al * Bh
#pragma unroll
            for (int fm = 0; fm < 2; fm++) {
                mma16816(acc[fm * 2 + 0], al4[fm], bh4 + 0);
                mma16816(acc[fm * 2 + 1], al4[fm], bh4 + 2);
            }
        }
    }

    const int er = lane >> 2;
    const int ec = (lane & 3) * 2;
#pragma unroll
    for (int fm = 0; fm < 2; fm++) {
#pragma unroll
        for (int fn = 0; fn < 2; fn++) {
            const size_t r0 = (size_t)(bm + m0 + fm * 16 + er) * GN + bn + n0 + fn * 8 + ec;
            const size_t r1 = r0 + (size_t)8 * GN;
            float* ac = acc[fm * 2 + fn];
            if (SPLIT_OUT) {
                uint32_t h0, l0, h1, l1;
                pack_hilo(ac[0], ac[1], h0, l0);
                pack_hilo(ac[2], ac[3], h1, l1);
                *reinterpret_cast<uint32_t*>(Ch + r0) = h0;
                *reinterpret_cast<uint32_t*>(Cl + r0) = l0;
                *reinterpret_cast<uint32_t*>(Ch + r1) = h1;
                *reinterpret_cast<uint32_t*>(Cl + r1) = l1;
            } else {
                *reinterpret_cast<float2*>(C + r0) = make_float2(ac[0], ac[1]);
                *reinterpret_cast<float2*>(C + r1) = make_float2(ac[2], ac[3]);
            }
        }
    }
}

__global__ __launch_bounds__(256, 4) void gemm_qkv()
{
    const int z = blockIdx.z;
    const __nv_bfloat16* Bh = (z == 0) ? g_wqh : (z == 1) ? g_wkh : g_wvh;
    const __nv_bfloat16* Bl = (z == 0) ? g_wql : (z == 1) ? g_wkl : g_wvl;
    __nv_bfloat16* Ch = (z == 0) ? g_qh : (z == 1) ? g_kh : g_vh;
    __nv_bfloat16* Cl = (z == 0) ? g_ql : (z == 1) ? g_kl : g_vl;
    gemm_core<true>(g_ah, g_al, Bh, Bl, nullptr, Ch, Cl);
}

__global__ __launch_bounds__(256, 4) void gemm_out(float* __restrict__ C)
{
    gemm_core<false>(g_oh, g_ol, g_woh, g_wol, C, nullptr, nullptr);
}

// =================== flash-style sparse attention (mma.sync, bf16x3) ========
// v2 (unchanged from R11/R12): Q fragments in registers, 64KB smem.
#define SA(r, c) ((uint32_t)((r) * 256 + (((c) ^ ((r) & 7)) * 16)))
#define ATTN_SMEM (4 * 16384)

__global__ __launch_bounds__(128, 2) void attn_mma(const int* __restrict__ rand_idx)
{
    extern __shared__ char smem[];
    const uint32_t sb = smem_u32(smem);
    const int tid  = threadIdx.x;
    const int lane = tid & 31;
    const int w    = tid >> 5;
    const int qb   = blockIdx.x;
    const int h    = blockIdx.y;

    int blist[6]; int nblk = 0;
    {
        int cand[6] = {qb, qb - 1, qb + 1, 0, NB - 1, rand_idx[qb]};
#pragma unroll
        for (int c = 0; c < 6; c++) {
            int b = cand[c];
            if (b < 0 || b >= NB) continue;
            bool dup = false;
            for (int d = 0; d < nblk; d++) dup |= (blist[d] == b);
            if (!dup) blist[nblk++] = b;
        }
    }

    const uint32_t KH = sb,             KL = sb + 16384;
    const uint32_t VH = sb + 2 * 16384, VL = sb + 3 * 16384;

    auto load_tile = [&](uint32_t dh, uint32_t dl,
                         const __nv_bfloat16* gh, const __nv_bfloat16* gl, int j) {
        const __nv_bfloat16* sh = gh + (size_t)(j * 64) * HID + h * HD;
        const __nv_bfloat16* sl = gl + (size_t)(j * 64) * HID + h * HD;
#pragma unroll
        for (int t = 0; t < 8; t++) {
            int cid = tid + t * 128;
            int r = cid >> 4, c = cid & 15;
            cpasync16(dh + SA(r, c), sh + (size_t)r * HID + c * 8);
            cpasync16(dl + SA(r, c), sl + (size_t)r * HID + c * 8);
        }
    };

    const int aRow  = w * 16 + (lane & 7) + ((lane >> 3) & 1) * 8;
    const int aCh   = (lane >> 4) & 1;
    const int bTile = lane >> 3;

    // ---- bootstrap: load Q into K buffer, hoist fragments to registers ----
    load_tile(KH, KL, g_qh, g_ql, qb);
    CP_COMMIT();
    CP_WAIT0();
    __syncthreads();
    uint32_t aqh[8][4], aql[8][4];
#pragma unroll
    for (int ks = 0; ks < 8; ks++) {
        LDSM_X4(aqh[ks][0], aqh[ks][1], aqh[ks][2], aqh[ks][3], KH + SA(aRow, 2 * ks + aCh));
        LDSM_X4(aql[ks][0], aql[ks][1], aql[ks][2], aql[ks][3], KL + SA(aRow, 2 * ks + aCh));
    }
    __syncthreads();   // all warps done reading Q; K buffer reusable

    load_tile(KH, KL, g_kh, g_kl, blist[0]);
    CP_COMMIT();

    float o[16][4];
#pragma unroll
    for (int i = 0; i < 16; i++)
#pragma unroll
        for (int j = 0; j < 4; j++) o[i][j] = 0.f;
    float m0 = -1e30f, m1 = -1e30f, l0 = 0.f, l1 = 0.f;

    for (int bi = 0; bi < nblk; bi++) {
        CP_WAIT0();
        __syncthreads();

        load_tile(VH, VL, g_vh, g_vl, blist[bi]);
        CP_COMMIT();

        float s[8][4];
#pragma unroll
        for (int i = 0; i < 8; i++)
#pragma unroll
            for (int j = 0; j < 4; j++) s[i][j] = 0.f;

#pragma unroll
        for (int ks = 0; ks < 8; ks++) {
#pragma unroll
            for (int fn = 0; fn < 8; fn += 2) {
                const int br = (fn + (bTile >> 1)) * 8 + (lane & 7);
                const int bc = 2 * ks + (bTile & 1);
                uint32_t kh4[4], kl4[4];
                LDSM_X4(kh4[0], kh4[1], kh4[2], kh4[3], KH + SA(br, bc));
                LDSM_X4(kl4[0], kl4[1], kl4[2], kl4[3], KL + SA(br, bc));
                mma16816(s[fn],     aqh[ks], kh4 + 0);
                mma16816(s[fn],     aqh[ks], kl4 + 0);
                mma16816(s[fn],     aql[ks], kh4 + 0);
                mma16816(s[fn + 1], aqh[ks], kh4 + 2);
                mma16816(s[fn + 1], aqh[ks], kl4 + 2);
                mma16816(s[fn + 1], aql[ks], kh4 + 2);
            }
        }
        __syncthreads();

        if (bi + 1 < nblk) {
            load_tile(KH, KL, g_kh, g_kl, blist[bi + 1]);
            CP_COMMIT();
        }

        float rmax0 = -1e30f, rmax1 = -1e30f;
#pragma unroll
        for (int fn = 0; fn < 8; fn++) {
            rmax0 = fmaxf(rmax0, fmaxf(s[fn][0], s[fn][1]));
            rmax1 = fmaxf(rmax1, fmaxf(s[fn][2], s[fn][3]));
        }
        rmax0 = fmaxf(rmax0, __shfl_xor_sync(0xffffffffu, rmax0, 1));
        rmax0 = fmaxf(rmax0, __shfl_xor_sync(0xffffffffu, rmax0, 2));
        rmax1 = fmaxf(rmax1, __shfl_xor_sync(0xffffffffu, rmax1, 1));
        rmax1 = fmaxf(rmax1, __shfl_xor_sync(0xffffffffu, rmax1, 2));
        const float mn0 = fmaxf(m0, rmax0 * SCALE);
        const float mn1 = fmaxf(m1, rmax1 * SCALE);
        const float corr0 = __expf(m0 - mn0);
        const float corr1 = __expf(m1 - mn1);
        float sum0 = 0.f, sum1 = 0.f;
#pragma unroll
        for (int fn = 0; fn < 8; fn++) {
            s[fn][0] = __expf(fmaf(s[fn][0], SCALE, -mn0));
            s[fn][1] = __expf(fmaf(s[fn][1], SCALE, -mn0));
            s[fn][2] = __expf(fmaf(s[fn][2], SCALE, -mn1));
            s[fn][3] = __expf(fmaf(s[fn][3], SCALE, -mn1));
            sum0 += s[fn][0] + s[fn][1];
            sum1 += s[fn][2] + s[fn][3];
        }
        sum0 += __shfl_xor_sync(0xffffffffu, sum0, 1);
        sum0 += __shfl_xor_sync(0xffffffffu, sum0, 2);
        sum1 += __shfl_xor_sync(0xffffffffu, sum1, 1);
        sum1 += __shfl_xor_sync(0xffffffffu, sum1, 2);
        l0 = l0 * corr0 + sum0; m0 = mn0;
        l1 = l1 * corr1 + sum1; m1 = mn1;

#pragma unroll
        for (int fd = 0; fd < 16; fd++) {
            o[fd][0] *= corr0; o[fd][1] *= corr0;
            o[fd][2] *= corr1; o[fd][3] *= corr1;
        }

        uint32_t ph[4][4], pl[4][4];
#pragma unroll
        for (int ks2 = 0; ks2 < 4; ks2++) {
            const int j0 = 2 * ks2, j1 = j0 + 1;
            pack_hilo(s[j0][0], s[j0][1], ph[ks2][0], pl[ks2][0]);
            pack_hilo(s[j0][2], s[j0][3], ph[ks2][1], pl[ks2][1]);
            pack_hilo(s[j1][0], s[j1][1], ph[ks2][2], pl[ks2][2]);
            pack_hilo(s[j1][2], s[j1][3], ph[ks2][3], pl[ks2][3]);
        }

        if (bi + 1 < nblk) CP_WAIT1(); else CP_WAIT0();
        __syncthreads();

#pragma unroll
        for (int ks2 = 0; ks2 < 4; ks2++) {
#pragma unroll
            for (int fd = 0; fd < 16; fd += 2) {
                const int vr = ks2 * 16 + (bTile & 1) * 8 + (lane & 7);
                const int vc = fd + (bTile >> 1);
                uint32_t vh4[4], vl4[4];
                LDSM_X4_T(vh4[0], vh4[1], vh4[2], vh4[3], VH + SA(vr, vc));
                LDSM_X4_T(vl4[0], vl4[1], vl4[2], vl4[3], VL + SA(vr, vc));
                mma16816(o[fd],     ph[ks2], vh4 + 0);
                mma16816(o[fd],     ph[ks2], vl4 + 0);
                mma16816(o[fd],     pl[ks2], vh4 + 0);
                mma16816(o[fd + 1], ph[ks2], vh4 + 2);
                mma16816(o[fd + 1], ph[ks2], vl4 + 2);
                mma16816(o[fd + 1], pl[ks2], vh4 + 2);
            }
        }
    }

    const float inv0 = 1.f / l0;
    const float inv1 = 1.f / l1;
    const int er = lane >> 2;
    const int ec = (lane & 3) * 2;
    const size_t row0 = (size_t)(qb * 64 + w * 16 + er) * HID;
    const size_t row1 = row0 + (size_t)8 * HID;
#pragma unroll
    for (int fd = 0; fd < 16; fd++) {
        const int col = h * HD + fd * 8 + ec;
        uint32_t h0, lo0, h1, lo1;
        pack_hilo(o[fd][0] * inv0, o[fd][1] * inv0, h0, lo0);
        pack_hilo(o[fd][2] * inv1, o[fd][3] * inv1, h1, lo1);
        *reinterpret_cast<uint32_t*>(g_oh + row0 + col) = h0;
        *reinterpret_cast<uint32_t*>(g_ol + row0 + col) = lo0;
        *reinterpret_cast<uint32_t*>(g_oh + row1 + col) = h1;
        *reinterpret_cast<uint32_t*>(g_ol + row1 + col) = lo1;
    }
}

// ---------------- launch -----------------------------------------------------
extern "C" void kernel_launch(void* const* d_in, const int* in_sizes, int n_in,
                              void* d_out, int out_size)
{
    const float* x    = (const float*)d_in[0];
    const int*   ridx = (const int*)d_in[1];
    const float* Wq   = (const float*)d_in[2];
    const float* Wk   = (const float*)d_in[3];
    const float* Wv   = (const float*)d_in[4];
    const float* Wo   = (const float*)d_in[5];
    float* out = (float*)d_out;

    cudaFuncSetAttribute(gemm_qkv, cudaFuncAttributeMaxDynamicSharedMemorySize, GEMM_SMEM);
    cudaFuncSetAttribute(gemm_out, cudaFuncAttributeMaxDynamicSharedMemorySize, GEMM_SMEM);
    cudaFuncSetAttribute(attn_mma, cudaFuncAttributeMaxDynamicSharedMemorySize, ATTN_SMEM);

    split_all<<<dim3(4096, 6), 256>>>(x, Wq, Wk, Wv, Wo);

    gemm_qkv<<<dim3(GN / 32, GM / 128, 3), 256, GEMM_SMEM>>>();

    attn_mma<<<dim3(NB, HEADS), 128, ATTN_SMEM>>>(ridx);

    gemm_out<<<dim3(GN / 32, GM / 128, 1), 256, GEMM_SMEM>>>(out);
}

// round 14
// speedup vs baseline: 1.4383x; 1.4383x over previous
#include <cuda_runtime.h>
#include <cuda_fp16.h>
#include <cstdint>
#include <cstddef>

#define SEQ    4096
#define HID    2048
#define HEADS  16
#define HD     128
#define NB     64
#define SCALE  0.08838834764831845f   // 1/sqrt(128)

#define GM 4096
#define GN 2048
#define GK 2048

// ---------------- scratch planes (device globals; no allocation allowed) ----
__device__ __half g_ah[SEQ * HID], g_al[SEQ * HID];   // activations
__device__ __half g_qh[SEQ * HID], g_ql[SEQ * HID];
__device__ __half g_kh[SEQ * HID], g_kl[SEQ * HID];
__device__ __half g_vh[SEQ * HID], g_vl[SEQ * HID];
__device__ __half g_oh[SEQ * HID], g_ol[SEQ * HID];   // attn output
__device__ __half g_wqh[HID * HID], g_wql[HID * HID];
__device__ __half g_wkh[HID * HID], g_wkl[HID * HID];
__device__ __half g_wvh[HID * HID], g_wvl[HID * HID];
__device__ __half g_woh[HID * HID], g_wol[HID * HID];

// =================== baseline-PTX helpers (sm_80+ ISA only) =================
__device__ __forceinline__ uint32_t smem_u32(const void* p) {
    uint32_t a;
    asm("{ .reg .u64 t; cvta.to.shared.u64 t, %1; cvt.u32.u64 %0, t; }" : "=r"(a) : "l"(p));
    return a;
}
__device__ __forceinline__ void cpasync16(uint32_t dst, const void* src) {
    asm volatile("cp.async.cg.shared.global [%0], [%1], 16;" :: "r"(dst), "l"(src));
}
#define CP_COMMIT() asm volatile("cp.async.commit_group;" ::: "memory")
#define CP_WAIT1()  asm volatile("cp.async.wait_group 1;" ::: "memory")
#define CP_WAIT0()  asm volatile("cp.async.wait_group 0;" ::: "memory")

#define LDSM_X4(r0, r1, r2, r3, addr) \
    asm volatile("ldmatrix.sync.aligned.m8n8.x4.shared.b16 {%0,%1,%2,%3}, [%4];" \
                 : "=r"(r0), "=r"(r1), "=r"(r2), "=r"(r3) : "r"(addr))
#define LDSM_X4_T(r0, r1, r2, r3, addr) \
    asm volatile("ldmatrix.sync.aligned.m8n8.x4.trans.shared.b16 {%0,%1,%2,%3}, [%4];" \
                 : "=r"(r0), "=r"(r1), "=r"(r2), "=r"(r3) : "r"(addr))

__device__ __forceinline__ void mma16816(float* d, const uint32_t* a, const uint32_t* b) {
    asm volatile("mma.sync.aligned.m16n8k16.row.col.f32.f16.f16.f32 "
                 "{%0,%1,%2,%3}, {%4,%5,%6,%7}, {%8,%9}, {%0,%1,%2,%3};"
                 : "+f"(d[0]), "+f"(d[1]), "+f"(d[2]), "+f"(d[3])
                 : "r"(a[0]), "r"(a[1]), "r"(a[2]), "r"(a[3]), "r"(b[0]), "r"(b[1]));
}

__device__ __forceinline__ uint32_t h2bits(__half2 v) {
    return *reinterpret_cast<uint32_t*>(&v);
}
__device__ __forceinline__ void pack_hilo(float x, float y, uint32_t& hi, uint32_t& lo) {
    __half2 h = __floats2half2_rn(x, y);
    float2 f = __half22float2(h);
    __half2 l = __floats2half2_rn(x - f.x, y - f.y);
    hi = h2bits(h); lo = h2bits(l);
}

// =================== fused fp32 -> fp16 hi/lo split ==========================
#define REG4 (1u << 20)

__global__ __launch_bounds__(256) void split_all(
    const float* __restrict__ x,  const float* __restrict__ wq,
    const float* __restrict__ wk, const float* __restrict__ wv,
    const float* __restrict__ wo)
{
    const int r = blockIdx.y;
    const float* src;
    __half *hi, *lo;
    size_t off = 0;
    if (r < 2)       { src = x;  hi = g_ah;  lo = g_al;  off = (size_t)r * REG4; }
    else if (r == 2) { src = wq; hi = g_wqh; lo = g_wql; }
    else if (r == 3) { src = wk; hi = g_wkh; lo = g_wkl; }
    else if (r == 4) { src = wv; hi = g_wvh; lo = g_wvl; }
    else             { src = wo; hi = g_woh; lo = g_wol; }

    const size_t i = off + (size_t)blockIdx.x * 256 + threadIdx.x;
    float4 v = reinterpret_cast<const float4*>(src)[i];
    uint32_t h01, l01, h23, l23;
    pack_hilo(v.x, v.y, h01, l01);
    pack_hilo(v.z, v.w, h23, l23);
    reinterpret_cast<uint2*>(hi)[i] = make_uint2(h01, h23);
    reinterpret_cast<uint2*>(lo)[i] = make_uint2(l01, l23);
}

// =================== fp16 hi/lo GEMM core (mma.sync, 128x64, 3 CTA/SM) ======
// R12-proven geometry: warp tile 32x32 (4m x 2n warps), 2-stage cp.async
// (24KB/stage), single sync per k-tile, __launch_bounds__(256,3).
// TERMS=3: C = Ah*Bh + Ah*Bl + Al*Bh  (error ~2^-22)
// TERMS=2: C = Ah*Bh + Ah*Bl          (drops Al*B, error ~2^-11; A-lo plane
//          never loaded -> fewer cp.async + ldsm + 1/3 fewer MMAs)
#define KTILE 32
#define NT (GK / KTILE)
#define ROWB 64
#define APLANE 8192                  // A: 128 rows * 64B
#define BPLANE 4096                  // B:  64 rows * 64B
#define STAGEB (2 * APLANE + 2 * BPLANE)   // 24 KB
#define GEMM_SMEM (2 * STAGEB)             // 48 KB
#define SWZ(r, c) ((uint32_t)((r) * ROWB + (((c) ^ (((r) >> 1) & 3)) * 16)))

template<int TERMS, bool SPLIT_OUT>
__device__ __forceinline__ void gemm_core(
    const __half* __restrict__ Ah, const __half* __restrict__ Al,
    const __half* __restrict__ Bh, const __half* __restrict__ Bl,
    float* __restrict__ C, __half* __restrict__ Ch, __half* __restrict__ Cl)
{
    extern __shared__ char smem[];
    const uint32_t sb = smem_u32(smem);
    const int tid  = threadIdx.x;
    const int lane = tid & 31;
    const int w    = tid >> 5;
    const int bm   = blockIdx.y * 128;
    const int bn   = blockIdx.x * 64;

    const int lr  = tid >> 1;
    const int lc0 = (tid & 1) << 1;
    const __half* gAh = Ah + (size_t)(bm + lr) * GK + lc0 * 8;
    const __half* gAl = Al + (size_t)(bm + lr) * GK + lc0 * 8;
    const uint32_t sA0 = SWZ(lr, lc0), sA1 = SWZ(lr, lc0 + 1);
    const int rb = tid >> 2;
    const int cb = tid & 3;
    const __half* gBh = Bh + (size_t)(bn + rb) * GK + cb * 8;
    const __half* gBl = Bl + (size_t)(bn + rb) * GK + cb * 8;
    const uint32_t sB = SWZ(rb, cb);

    auto load_stage = [&](int t, int st) {
        const uint32_t base = sb + st * STAGEB;
        const int ko = t * KTILE;
        cpasync16(base + sA0, gAh + ko);
        cpasync16(base + sA1, gAh + ko + 8);
        if (TERMS == 3) {
            cpasync16(base + APLANE + sA0, gAl + ko);
            cpasync16(base + APLANE + sA1, gAl + ko + 8);
        }
        cpasync16(base + 2 * APLANE + sB, gBh + ko);
        cpasync16(base + 2 * APLANE + BPLANE + sB, gBl + ko);
    };

    const int m0 = (w & 3) * 32;     // 4 warps over M
    const int n0 = (w >> 2) * 32;    // 2 warps over N

    const int xrA = ((lane >> 3) & 1) * 8 + (lane & 7);
    const int xcA = (lane >> 4) & 1;
    const int xrB = ((lane >> 4) & 1) * 8 + (lane & 7);
    const int xcB = (lane >> 3) & 1;

    float acc[8][4];
#pragma unroll
    for (int i = 0; i < 8; i++)
#pragma unroll
        for (int j = 0; j < 4; j++) acc[i][j] = 0.f;

    load_stage(0, 0);
    CP_COMMIT();

    for (int t = 0; t < NT; t++) {
        CP_WAIT0();
        __syncthreads();

        if (t + 1 < NT) {
            load_stage(t + 1, (t + 1) & 1);
            CP_COMMIT();
        }

        const uint32_t stage = sb + (t & 1) * STAGEB;
#pragma unroll
        for (int ks = 0; ks < 2; ks++) {
            uint32_t ah4[2][4], al4[2][4];
#pragma unroll
            for (int fm = 0; fm < 2; fm++) {
                const uint32_t sw = SWZ(m0 + fm * 16 + xrA, 2 * ks + xcA);
                LDSM_X4(ah4[fm][0], ah4[fm][1], ah4[fm][2], ah4[fm][3], stage + sw);
                if (TERMS == 3)
                    LDSM_X4(al4[fm][0], al4[fm][1], al4[fm][2], al4[fm][3],
                            stage + APLANE + sw);
            }
            uint32_t bh4[2][4], bl4[2][4];
#pragma unroll
            for (int fnp = 0; fnp < 2; fnp++) {
                const uint32_t sw = SWZ(n0 + fnp * 16 + xrB, 2 * ks + xcB);
                LDSM_X4(bh4[fnp][0], bh4[fnp][1], bh4[fnp][2], bh4[fnp][3],
                        stage + 2 * APLANE + sw);
                LDSM_X4(bl4[fnp][0], bl4[fnp][1], bl4[fnp][2], bl4[fnp][3],
                        stage + 2 * APLANE + BPLANE + sw);
            }
            // combo 1: Ah * Bh
#pragma unroll
            for (int fm = 0; fm < 2; fm++)
#pragma unroll
                for (int fnp = 0; fnp < 2; fnp++) {
                    mma16816(acc[fm * 4 + 2 * fnp],     ah4[fm], bh4[fnp] + 0);
                    mma16816(acc[fm * 4 + 2 * fnp + 1], ah4[fm], bh4[fnp] + 2);
                }
            // combo 2: Ah * Bl
#pragma unroll
            for (int fm = 0; fm < 2; fm++)
#pragma unroll
                for (int fnp = 0; fnp < 2; fnp++) {
                    mma16816(acc[fm * 4 + 2 * fnp],     ah4[fm], bl4[fnp] + 0);
                    mma16816(acc[fm * 4 + 2 * fnp + 1], ah4[fm], bl4[fnp] + 2);
                }
            // combo 3: Al * Bh (3-term only)
            if (TERMS == 3) {
#pragma unroll
                for (int fm = 0; fm < 2; fm++)
#pragma unroll
                    for (int fnp = 0; fnp < 2; fnp++) {
                        mma16816(acc[fm * 4 + 2 * fnp],     al4[fm], bh4[fnp] + 0);
                        mma16816(acc[fm * 4 + 2 * fnp + 1], al4[fm], bh4[fnp] + 2);
                    }
            }
        }
    }

    const int er = lane >> 2;
    const int ec = (lane & 3) * 2;
#pragma unroll
    for (int fm = 0; fm < 2; fm++) {
#pragma unroll
        for (int fn = 0; fn < 4; fn++) {
            const size_t r0 = (size_t)(bm + m0 + fm * 16 + er) * GN + bn + n0 + fn * 8 + ec;
            const size_t r1 = r0 + (size_t)8 * GN;
            float* ac = acc[fm * 4 + fn];
            if (SPLIT_OUT) {
                uint32_t h0, l0, h1, l1;
                pack_hilo(ac[0], ac[1], h0, l0);
                pack_hilo(ac[2], ac[3], h1, l1);
                *reinterpret_cast<uint32_t*>(Ch + r0) = h0;
                *reinterpret_cast<uint32_t*>(Cl + r0) = l0;
                *reinterpret_cast<uint32_t*>(Ch + r1) = h1;
                *reinterpret_cast<uint32_t*>(Cl + r1) = l1;
            } else {
                *reinterpret_cast<float2*>(C + r0) = make_float2(ac[0], ac[1]);
                *reinterpret_cast<float2*>(C + r1) = make_float2(ac[2], ac[3]);
            }
        }
    }
}

// QKV: Q,K use 3-term (softmax amplifies q/k errors); V uses 2-term (linear path)
__global__ __launch_bounds__(256, 3) void gemm_qkv()
{
    const int z = blockIdx.z;
    if (z == 0)
        gemm_core<3, true>(g_ah, g_al, g_wqh, g_wql, nullptr, g_qh, g_ql);
    else if (z == 1)
        gemm_core<3, true>(g_ah, g_al, g_wkh, g_wkl, nullptr, g_kh, g_kl);
    else
        gemm_core<2, true>(g_ah, g_al, g_wvh, g_wvl, nullptr, g_vh, g_vl);
}

__global__ __launch_bounds__(256, 3) void gemm_out(float* __restrict__ C)
{
    gemm_core<2, false>(g_oh, g_ol, g_woh, g_wol, C, nullptr, nullptr);
}

// =================== flash-style sparse attention (mma.sync, fp16 3-term) ===
// Structure unchanged from R11/R12 best; planes are now fp16 (more accurate).
#define SA(r, c) ((uint32_t)((r) * 256 + (((c) ^ ((r) & 7)) * 16)))
#define ATTN_SMEM (4 * 16384)

__global__ __launch_bounds__(128, 2) void attn_mma(const int* __restrict__ rand_idx)
{
    extern __shared__ char smem[];
    const uint32_t sb = smem_u32(smem);
    const int tid  = threadIdx.x;
    const int lane = tid & 31;
    const int w    = tid >> 5;
    const int qb   = blockIdx.x;
    const int h    = blockIdx.y;

    int blist[6]; int nblk = 0;
    {
        int cand[6] = {qb, qb - 1, qb + 1, 0, NB - 1, rand_idx[qb]};
#pragma unroll
        for (int c = 0; c < 6; c++) {
            int b = cand[c];
            if (b < 0 || b >= NB) continue;
            bool dup = false;
            for (int d = 0; d < nblk; d++) dup |= (blist[d] == b);
            if (!dup) blist[nblk++] = b;
        }
    }

    const uint32_t KH = sb,             KL = sb + 16384;
    const uint32_t VH = sb + 2 * 16384, VL = sb + 3 * 16384;

    auto load_tile = [&](uint32_t dh, uint32_t dl,
                         const __half* gh, const __half* gl, int j) {
        const __half* sh = gh + (size_t)(j * 64) * HID + h * HD;
        const __half* sl = gl + (size_t)(j * 64) * HID + h * HD;
#pragma unroll
        for (int t = 0; t < 8; t++) {
            int cid = tid + t * 128;
            int r = cid >> 4, c = cid & 15;
            cpasync16(dh + SA(r, c), sh + (size_t)r * HID + c * 8);
            cpasync16(dl + SA(r, c), sl + (size_t)r * HID + c * 8);
        }
    };

    const int aRow  = w * 16 + (lane & 7) + ((lane >> 3) & 1) * 8;
    const int aCh   = (lane >> 4) & 1;
    const int bTile = lane >> 3;

    // ---- bootstrap: load Q into K buffer, hoist fragments to registers ----
    load_tile(KH, KL, g_qh, g_ql, qb);
    CP_COMMIT();
    CP_WAIT0();
    __syncthreads();
    uint32_t aqh[8][4], aql[8][4];
#pragma unroll
    for (int ks = 0; ks < 8; ks++) {
        LDSM_X4(aqh[ks][0], aqh[ks][1], aqh[ks][2], aqh[ks][3], KH + SA(aRow, 2 * ks + aCh));
        LDSM_X4(aql[ks][0], aql[ks][1], aql[ks][2], aql[ks][3], KL + SA(aRow, 2 * ks + aCh));
    }
    __syncthreads();

    load_tile(KH, KL, g_kh, g_kl, blist[0]);
    CP_COMMIT();

    float o[16][4];
#pragma unroll
    for (int i = 0; i < 16; i++)
#pragma unroll
        for (int j = 0; j < 4; j++) o[i][j] = 0.f;
    float m0 = -1e30f, m1 = -1e30f, l0 = 0.f, l1 = 0.f;

    for (int bi = 0; bi < nblk; bi++) {
        CP_WAIT0();
        __syncthreads();

        load_tile(VH, VL, g_vh, g_vl, blist[bi]);
        CP_COMMIT();

        float s[8][4];
#pragma unroll
        for (int i = 0; i < 8; i++)
#pragma unroll
            for (int j = 0; j < 4; j++) s[i][j] = 0.f;

#pragma unroll
        for (int ks = 0; ks < 8; ks++) {
#pragma unroll
            for (int fn = 0; fn < 8; fn += 2) {
                const int br = (fn + (bTile >> 1)) * 8 + (lane & 7);
                const int bc = 2 * ks + (bTile & 1);
                uint32_t kh4[4], kl4[4];
                LDSM_X4(kh4[0], kh4[1], kh4[2], kh4[3], KH + SA(br, bc));
                LDSM_X4(kl4[0], kl4[1], kl4[2], kl4[3], KL + SA(br, bc));
                mma16816(s[fn],     aqh[ks], kh4 + 0);
                mma16816(s[fn],     aqh[ks], kl4 + 0);
                mma16816(s[fn],     aql[ks], kh4 + 0);
                mma16816(s[fn + 1], aqh[ks], kh4 + 2);
                mma16816(s[fn + 1], aqh[ks], kl4 + 2);
                mma16816(s[fn + 1], aql[ks], kh4 + 2);
            }
        }
        __syncthreads();

        if (bi + 1 < nblk) {
            load_tile(KH, KL, g_kh, g_kl, blist[bi + 1]);
            CP_COMMIT();
        }

        float rmax0 = -1e30f, rmax1 = -1e30f;
#pragma unroll
        for (int fn = 0; fn < 8; fn++) {
            rmax0 = fmaxf(rmax0, fmaxf(s[fn][0], s[fn][1]));
            rmax1 = fmaxf(rmax1, fmaxf(s[fn][2], s[fn][3]));
        }
        rmax0 = fmaxf(rmax0, __shfl_xor_sync(0xffffffffu, rmax0, 1));
        rmax0 = fmaxf(rmax0, __shfl_xor_sync(0xffffffffu, rmax0, 2));
        rmax1 = fmaxf(rmax1, __shfl_xor_sync(0xffffffffu, rmax1, 1));
        rmax1 = fmaxf(rmax1, __shfl_xor_sync(0xffffffffu, rmax1, 2));
        const float mn0 = fmaxf(m0, rmax0 * SCALE);
        const float mn1 = fmaxf(m1, rmax1 * SCALE);
        const float corr0 = __expf(m0 - mn0);
        const float corr1 = __expf(m1 - mn1);
        float sum0 = 0.f, sum1 = 0.f;
#pragma unroll
        for (int fn = 0; fn < 8; fn++) {
            s[fn][0] = __expf(fmaf(s[fn][0], SCALE, -mn0));
            s[fn][1] = __expf(fmaf(s[fn][1], SCALE, -mn0));
            s[fn][2] = __expf(fmaf(s[fn][2], SCALE, -mn1));
            s[fn][3] = __expf(fmaf(s[fn][3], SCALE, -mn1));
            sum0 += s[fn][0] + s[fn][1];
            sum1 += s[fn][2] + s[fn][3];
        }
        sum0 += __shfl_xor_sync(0xffffffffu, sum0, 1);
        sum0 += __shfl_xor_sync(0xffffffffu, sum0, 2);
        sum1 += __shfl_xor_sync(0xffffffffu, sum1, 1);
        sum1 += __shfl_xor_sync(0xffffffffu, sum1, 2);
        l0 = l0 * corr0 + sum0; m0 = mn0;
        l1 = l1 * corr1 + sum1; m1 = mn1;

#pragma unroll
        for (int fd = 0; fd < 16; fd++) {
            o[fd][0] *= corr0; o[fd][1] *= corr0;
            o[fd][2] *= corr1; o[fd][3] *= corr1;
        }

        uint32_t ph[4][4], pl[4][4];
#pragma unroll
        for (int ks2 = 0; ks2 < 4; ks2++) {
            const int j0 = 2 * ks2, j1 = j0 + 1;
            pack_hilo(s[j0][0], s[j0][1], ph[ks2][0], pl[ks2][0]);
            pack_hilo(s[j0][2], s[j0][3], ph[ks2][1], pl[ks2][1]);
            pack_hilo(s[j1][0], s[j1][1], ph[ks2][2], pl[ks2][2]);
            pack_hilo(s[j1][2], s[j1][3], ph[ks2][3], pl[ks2][3]);
        }

        if (bi + 1 < nblk) CP_WAIT1(); else CP_WAIT0();
        __syncthreads();

#pragma unroll
        for (int ks2 = 0; ks2 < 4; ks2++) {
#pragma unroll
            for (int fd = 0; fd < 16; fd += 2) {
                const int vr = ks2 * 16 + (bTile & 1) * 8 + (lane & 7);
                const int vc = fd + (bTile >> 1);
                uint32_t vh4[4], vl4[4];
                LDSM_X4_T(vh4[0], vh4[1], vh4[2], vh4[3], VH + SA(vr, vc));
                LDSM_X4_T(vl4[0], vl4[1], vl4[2], vl4[3], VL + SA(vr, vc));
                mma16816(o[fd],     ph[ks2], vh4 + 0);
                mma16816(o[fd],     ph[ks2], vl4 + 0);
                mma16816(o[fd],     pl[ks2], vh4 + 0);
                mma16816(o[fd + 1], ph[ks2], vh4 + 2);
                mma16816(o[fd + 1], ph[ks2], vl4 + 2);
                mma16816(o[fd + 1], pl[ks2], vh4 + 2);
            }
        }
    }

    const float inv0 = 1.f / l0;
    const float inv1 = 1.f / l1;
    const int er = lane >> 2;
    const int ec = (lane & 3) * 2;
    const size_t row0 = (size_t)(qb * 64 + w * 16 + er) * HID;
    const size_t row1 = row0 + (size_t)8 * HID;
#pragma unroll
    for (int fd = 0; fd < 16; fd++) {
        const int col = h * HD + fd * 8 + ec;
        uint32_t h0, lo0, h1, lo1;
        pack_hilo(o[fd][0] * inv0, o[fd][1] * inv0, h0, lo0);
        pack_hilo(o[fd][2] * inv1, o[fd][3] * inv1, h1, lo1);
        *reinterpret_cast<uint32_t*>(g_oh + row0 + col) = h0;
        *reinterpret_cast<uint32_t*>(g_ol + row0 + col) = lo0;
        *reinterpret_cast<uint32_t*>(g_oh + row1 + col) = h1;
        *reinterpret_cast<uint32_t*>(g_ol + row1 + col) = lo1;
    }
}

// ---------------- launch -----------------------------------------------------
extern "C" void kernel_launch(void* const* d_in, const int* in_sizes, int n_in,
                              void* d_out, int out_size)
{
    const float* x    = (const float*)d_in[0];
    const int*   ridx = (const int*)d_in[1];
    const float* Wq   = (const float*)d_in[2];
    const float* Wk   = (const float*)d_in[3];
    const float* Wv   = (const float*)d_in[4];
    const float* Wo   = (const float*)d_in[5];
    float* out = (float*)d_out;

    cudaFuncSetAttribute(gemm_qkv, cudaFuncAttributeMaxDynamicSharedMemorySize, GEMM_SMEM);
    cudaFuncSetAttribute(gemm_out, cudaFuncAttributeMaxDynamicSharedMemorySize, GEMM_SMEM);
    cudaFuncSetAttribute(attn_mma, cudaFuncAttributeMaxDynamicSharedMemorySize, ATTN_SMEM);

    split_all<<<dim3(4096, 6), 256>>>(x, Wq, Wk, Wv, Wo);

    gemm_qkv<<<dim3(GN / 64, GM / 128, 3), 256, GEMM_SMEM>>>();

    attn_mma<<<dim3(NB, HEADS), 128, ATTN_SMEM>>>(ridx);

    gemm_out<<<dim3(GN / 64, GM / 128, 1), 256, GEMM_SMEM>>>(out);
}

// round 15
// speedup vs baseline: 1.8583x; 1.2920x over previous
#include <cuda_runtime.h>
#include <cuda_fp16.h>
#include <cstdint>
#include <cstddef>

#define SEQ    4096
#define HID    2048
#define HEADS  16
#define HD     128
#define NB     64
#define SCALE  0.08838834764831845f   // 1/sqrt(128)

#define GM 4096
#define GN 2048
#define GK 2048

// ---------------- scratch planes (device globals; no allocation allowed) ----
__device__ __half g_ah[SEQ * HID];                    // activations (hi only)
__device__ __half g_qh[SEQ * HID], g_ql[SEQ * HID];
__device__ __half g_kh[SEQ * HID], g_kl[SEQ * HID];
__device__ __half g_vh[SEQ * HID], g_vl[SEQ * HID];   // vl written, unused
__device__ __half g_oh[SEQ * HID];                    // attn output (hi only)
__device__ __half g_wqh[HID * HID], g_wql[HID * HID];
__device__ __half g_wkh[HID * HID], g_wkl[HID * HID];
__device__ __half g_wvh[HID * HID], g_wvl[HID * HID];
__device__ __half g_woh[HID * HID], g_wol[HID * HID];

// =================== baseline-PTX helpers (sm_80+ ISA only) =================
__device__ __forceinline__ uint32_t smem_u32(const void* p) {
    uint32_t a;
    asm("{ .reg .u64 t; cvta.to.shared.u64 t, %1; cvt.u32.u64 %0, t; }" : "=r"(a) : "l"(p));
    return a;
}
__device__ __forceinline__ void cpasync16(uint32_t dst, const void* src) {
    asm volatile("cp.async.cg.shared.global [%0], [%1], 16;" :: "r"(dst), "l"(src));
}
#define CP_COMMIT() asm volatile("cp.async.commit_group;" ::: "memory")
#define CP_WAIT1()  asm volatile("cp.async.wait_group 1;" ::: "memory")
#define CP_WAIT0()  asm volatile("cp.async.wait_group 0;" ::: "memory")

#define LDSM_X4(r0, r1, r2, r3, addr) \
    asm volatile("ldmatrix.sync.aligned.m8n8.x4.shared.b16 {%0,%1,%2,%3}, [%4];" \
                 : "=r"(r0), "=r"(r1), "=r"(r2), "=r"(r3) : "r"(addr))
#define LDSM_X4_T(r0, r1, r2, r3, addr) \
    asm volatile("ldmatrix.sync.aligned.m8n8.x4.trans.shared.b16 {%0,%1,%2,%3}, [%4];" \
                 : "=r"(r0), "=r"(r1), "=r"(r2), "=r"(r3) : "r"(addr))

__device__ __forceinline__ void mma16816(float* d, const uint32_t* a, const uint32_t* b) {
    asm volatile("mma.sync.aligned.m16n8k16.row.col.f32.f16.f16.f32 "
                 "{%0,%1,%2,%3}, {%4,%5,%6,%7}, {%8,%9}, {%0,%1,%2,%3};"
                 : "+f"(d[0]), "+f"(d[1]), "+f"(d[2]), "+f"(d[3])
                 : "r"(a[0]), "r"(a[1]), "r"(a[2]), "r"(a[3]), "r"(b[0]), "r"(b[1]));
}

__device__ __forceinline__ uint32_t h2bits(__half2 v) {
    return *reinterpret_cast<uint32_t*>(&v);
}
__device__ __forceinline__ void pack_hilo(float x, float y, uint32_t& hi, uint32_t& lo) {
    __half2 h = __floats2half2_rn(x, y);
    float2 f = __half22float2(h);
    __half2 l = __floats2half2_rn(x - f.x, y - f.y);
    hi = h2bits(h); lo = h2bits(l);
}

// =================== fused fp32 -> fp16 hi/lo split ==========================
// x regions (r<2): hi plane only (lo never consumed by 2-term GEMMs).
#define REG4 (1u << 20)

__global__ __launch_bounds__(256) void split_all(
    const float* __restrict__ x,  const float* __restrict__ wq,
    const float* __restrict__ wk, const float* __restrict__ wv,
    const float* __restrict__ wo)
{
    const int r = blockIdx.y;
    const float* src;
    __half *hi, *lo = nullptr;
    size_t off = 0;
    if (r < 2)       { src = x;  hi = g_ah;               off = (size_t)r * REG4; }
    else if (r == 2) { src = wq; hi = g_wqh; lo = g_wql; }
    else if (r == 3) { src = wk; hi = g_wkh; lo = g_wkl; }
    else if (r == 4) { src = wv; hi = g_wvh; lo = g_wvl; }
    else             { src = wo; hi = g_woh; lo = g_wol; }

    const size_t i = off + (size_t)blockIdx.x * 256 + threadIdx.x;
    float4 v = reinterpret_cast<const float4*>(src)[i];
    uint32_t h01, l01, h23, l23;
    pack_hilo(v.x, v.y, h01, l01);
    pack_hilo(v.z, v.w, h23, l23);
    reinterpret_cast<uint2*>(hi)[i] = make_uint2(h01, h23);
    if (r >= 2)
        reinterpret_cast<uint2*>(lo)[i] = make_uint2(l01, l23);
}

// =================== fp16 2-term GEMM core (mma.sync, 128x64, 3 CTA/SM) =====
// R12/R14-proven geometry: warp tile 32x32 (4m x 2n warps), 2-stage cp.async,
// single sync per k-tile, __launch_bounds__(256,3).
// C = Ah*Bh + Ah*Bl   (A effectively fp16-rounded; B fully compensated)
#define KTILE 32
#define NT (GK / KTILE)
#define ROWB 64
#define APLANE 8192                  // A: 128 rows * 64B
#define BPLANE 4096                  // B:  64 rows * 64B
#define STAGEB (APLANE + 2 * BPLANE)       // 16 KB (Ah, Bh, Bl)
#define GEMM_SMEM (2 * STAGEB)             // 32 KB
#define SWZ(r, c) ((uint32_t)((r) * ROWB + (((c) ^ (((r) >> 1) & 3)) * 16)))

template<bool SPLIT_OUT>
__device__ __forceinline__ void gemm_core(
    const __half* __restrict__ Ah,
    const __half* __restrict__ Bh, const __half* __restrict__ Bl,
    float* __restrict__ C, __half* __restrict__ Ch, __half* __restrict__ Cl)
{
    extern __shared__ char smem[];
    const uint32_t sb = smem_u32(smem);
    const int tid  = threadIdx.x;
    const int lane = tid & 31;
    const int w    = tid >> 5;
    const int bm   = blockIdx.y * 128;
    const int bn   = blockIdx.x * 64;

    const int lr  = tid >> 1;
    const int lc0 = (tid & 1) << 1;
    const __half* gAh = Ah + (size_t)(bm + lr) * GK + lc0 * 8;
    const uint32_t sA0 = SWZ(lr, lc0), sA1 = SWZ(lr, lc0 + 1);
    const int rb = tid >> 2;
    const int cb = tid & 3;
    const __half* gBh = Bh + (size_t)(bn + rb) * GK + cb * 8;
    const __half* gBl = Bl + (size_t)(bn + rb) * GK + cb * 8;
    const uint32_t sB = SWZ(rb, cb);

    auto load_stage = [&](int t, int st) {
        const uint32_t base = sb + st * STAGEB;
        const int ko = t * KTILE;
        cpasync16(base + sA0, gAh + ko);
        cpasync16(base + sA1, gAh + ko + 8);
        cpasync16(base + APLANE + sB, gBh + ko);
        cpasync16(base + APLANE + BPLANE + sB, gBl + ko);
    };

    const int m0 = (w & 3) * 32;     // 4 warps over M
    const int n0 = (w >> 2) * 32;    // 2 warps over N

    const int xrA = ((lane >> 3) & 1) * 8 + (lane & 7);
    const int xcA = (lane >> 4) & 1;
    const int xrB = ((lane >> 4) & 1) * 8 + (lane & 7);
    const int xcB = (lane >> 3) & 1;

    float acc[8][4];
#pragma unroll
    for (int i = 0; i < 8; i++)
#pragma unroll
        for (int j = 0; j < 4; j++) acc[i][j] = 0.f;

    load_stage(0, 0);
    CP_COMMIT();

    for (int t = 0; t < NT; t++) {
        CP_WAIT0();
        __syncthreads();

        if (t + 1 < NT) {
            load_stage(t + 1, (t + 1) & 1);
            CP_COMMIT();
        }

        const uint32_t stage = sb + (t & 1) * STAGEB;
#pragma unroll
        for (int ks = 0; ks < 2; ks++) {
            uint32_t ah4[2][4];
#pragma unroll
            for (int fm = 0; fm < 2; fm++) {
                const uint32_t sw = SWZ(m0 + fm * 16 + xrA, 2 * ks + xcA);
                LDSM_X4(ah4[fm][0], ah4[fm][1], ah4[fm][2], ah4[fm][3], stage + sw);
            }
            uint32_t bh4[2][4], bl4[2][4];
#pragma unroll
            for (int fnp = 0; fnp < 2; fnp++) {
                const uint32_t sw = SWZ(n0 + fnp * 16 + xrB, 2 * ks + xcB);
                LDSM_X4(bh4[fnp][0], bh4[fnp][1], bh4[fnp][2], bh4[fnp][3],
                        stage + APLANE + sw);
                LDSM_X4(bl4[fnp][0], bl4[fnp][1], bl4[fnp][2], bl4[fnp][3],
                        stage + APLANE + BPLANE + sw);
            }
            // combo 1: Ah * Bh
#pragma unroll
            for (int fm = 0; fm < 2; fm++)
#pragma unroll
                for (int fnp = 0; fnp < 2; fnp++) {
                    mma16816(acc[fm * 4 + 2 * fnp],     ah4[fm], bh4[fnp] + 0);
                    mma16816(acc[fm * 4 + 2 * fnp + 1], ah4[fm], bh4[fnp] + 2);
                }
            // combo 2: Ah * Bl
#pragma unroll
            for (int fm = 0; fm < 2; fm++)
#pragma unroll
                for (int fnp = 0; fnp < 2; fnp++) {
                    mma16816(acc[fm * 4 + 2 * fnp],     ah4[fm], bl4[fnp] + 0);
                    mma16816(acc[fm * 4 + 2 * fnp + 1], ah4[fm], bl4[fnp] + 2);
                }
        }
    }

    const int er = lane >> 2;
    const int ec = (lane & 3) * 2;
#pragma unroll
    for (int fm = 0; fm < 2; fm++) {
#pragma unroll
        for (int fn = 0; fn < 4; fn++) {
            const size_t r0 = (size_t)(bm + m0 + fm * 16 + er) * GN + bn + n0 + fn * 8 + ec;
            const size_t r1 = r0 + (size_t)8 * GN;
            float* ac = acc[fm * 4 + fn];
            if (SPLIT_OUT) {
                uint32_t h0, l0, h1, l1;
                pack_hilo(ac[0], ac[1], h0, l0);
                pack_hilo(ac[2], ac[3], h1, l1);
                *reinterpret_cast<uint32_t*>(Ch + r0) = h0;
                *reinterpret_cast<uint32_t*>(Cl + r0) = l0;
                *reinterpret_cast<uint32_t*>(Ch + r1) = h1;
                *reinterpret_cast<uint32_t*>(Cl + r1) = l1;
            } else {
                *reinterpret_cast<float2*>(C + r0) = make_float2(ac[0], ac[1]);
                *reinterpret_cast<float2*>(C + r1) = make_float2(ac[2], ac[3]);
            }
        }
    }
}

__global__ __launch_bounds__(256, 3) void gemm_qkv()
{
    const int z = blockIdx.z;
    if (z == 0)
        gemm_core<true>(g_ah, g_wqh, g_wql, nullptr, g_qh, g_ql);
    else if (z == 1)
        gemm_core<true>(g_ah, g_wkh, g_wkl, nullptr, g_kh, g_kl);
    else
        gemm_core<true>(g_ah, g_wvh, g_wvl, nullptr, g_vh, g_vl);
}

__global__ __launch_bounds__(256, 3) void gemm_out(float* __restrict__ C)
{
    gemm_core<false>(g_oh, g_woh, g_wol, C, nullptr, nullptr);
}

// =================== flash-style sparse attention (mma.sync, fp16) ==========
// S = (Qh+Ql)(Kh+Kl)^T 3-term (compensates storage quantization of q,k).
// PV = (Ph+Pl)*Vh  (V's lo plane dropped; error ~2e-4).
// Q fragments hoisted to registers; smem = Kh,Kl,Vh (48KB).
#define SA(r, c) ((uint32_t)((r) * 256 + (((c) ^ ((r) & 7)) * 16)))
#define ATTN_SMEM (3 * 16384)

__global__ __launch_bounds__(128, 2) void attn_mma(const int* __restrict__ rand_idx)
{
    extern __shared__ char smem[];
    const uint32_t sb = smem_u32(smem);
    const int tid  = threadIdx.x;
    const int lane = tid & 31;
    const int w    = tid >> 5;
    const int qb   = blockIdx.x;
    const int h    = blockIdx.y;

    int blist[6]; int nblk = 0;
    {
        int cand[6] = {qb, qb - 1, qb + 1, 0, NB - 1, rand_idx[qb]};
#pragma unroll
        for (int c = 0; c < 6; c++) {
            int b = cand[c];
            if (b < 0 || b >= NB) continue;
            bool dup = false;
            for (int d = 0; d < nblk; d++) dup |= (blist[d] == b);
            if (!dup) blist[nblk++] = b;
        }
    }

    const uint32_t KH = sb, KL = sb + 16384, VH = sb + 2 * 16384;

    auto load_pair = [&](uint32_t dh, uint32_t dl,
                         const __half* gh, const __half* gl, int j) {
        const __half* sh = gh + (size_t)(j * 64) * HID + h * HD;
        const __half* sl = gl + (size_t)(j * 64) * HID + h * HD;
#pragma unroll
        for (int t = 0; t < 8; t++) {
            int cid = tid + t * 128;
            int r = cid >> 4, c = cid & 15;
            cpasync16(dh + SA(r, c), sh + (size_t)r * HID + c * 8);
            cpasync16(dl + SA(r, c), sl + (size_t)r * HID + c * 8);
        }
    };
    auto load_one = [&](uint32_t dh, const __half* gh, int j) {
        const __half* sh = gh + (size_t)(j * 64) * HID + h * HD;
#pragma unroll
        for (int t = 0; t < 8; t++) {
            int cid = tid + t * 128;
            int r = cid >> 4, c = cid & 15;
            cpasync16(dh + SA(r, c), sh + (size_t)r * HID + c * 8);
        }
    };

    const int aRow  = w * 16 + (lane & 7) + ((lane >> 3) & 1) * 8;
    const int aCh   = (lane >> 4) & 1;
    const int bTile = lane >> 3;

    // ---- bootstrap: load Q into K buffers, hoist fragments to registers ----
    load_pair(KH, KL, g_qh, g_ql, qb);
    CP_COMMIT();
    CP_WAIT0();
    __syncthreads();
    uint32_t aqh[8][4], aql[8][4];
#pragma unroll
    for (int ks = 0; ks < 8; ks++) {
        LDSM_X4(aqh[ks][0], aqh[ks][1], aqh[ks][2], aqh[ks][3], KH + SA(aRow, 2 * ks + aCh));
        LDSM_X4(aql[ks][0], aql[ks][1], aql[ks][2], aql[ks][3], KL + SA(aRow, 2 * ks + aCh));
    }
    __syncthreads();

    load_pair(KH, KL, g_kh, g_kl, blist[0]);
    CP_COMMIT();

    float o[16][4];
#pragma unroll
    for (int i = 0; i < 16; i++)
#pragma unroll
        for (int j = 0; j < 4; j++) o[i][j] = 0.f;
    float m0 = -1e30f, m1 = -1e30f, l0 = 0.f, l1 = 0.f;

    for (int bi = 0; bi < nblk; bi++) {
        CP_WAIT0();
        __syncthreads();

        load_one(VH, g_vh, blist[bi]);
        CP_COMMIT();

        float s[8][4];
#pragma unroll
        for (int i = 0; i < 8; i++)
#pragma unroll
            for (int j = 0; j < 4; j++) s[i][j] = 0.f;

#pragma unroll
        for (int ks = 0; ks < 8; ks++) {
#pragma unroll
            for (int fn = 0; fn < 8; fn += 2) {
                const int br = (fn + (bTile >> 1)) * 8 + (lane & 7);
                const int bc = 2 * ks + (bTile & 1);
                uint32_t kh4[4], kl4[4];
                LDSM_X4(kh4[0], kh4[1], kh4[2], kh4[3], KH + SA(br, bc));
                LDSM_X4(kl4[0], kl4[1], kl4[2], kl4[3], KL + SA(br, bc));
                mma16816(s[fn],     aqh[ks], kh4 + 0);
                mma16816(s[fn],     aqh[ks], kl4 + 0);
                mma16816(s[fn],     aql[ks], kh4 + 0);
                mma16816(s[fn + 1], aqh[ks], kh4 + 2);
                mma16816(s[fn + 1], aqh[ks], kl4 + 2);
                mma16816(s[fn + 1], aql[ks], kh4 + 2);
            }
        }
        __syncthreads();

        if (bi + 1 < nblk) {
            load_pair(KH, KL, g_kh, g_kl, blist[bi + 1]);
            CP_COMMIT();
        }

        float rmax0 = -1e30f, rmax1 = -1e30f;
#pragma unroll
        for (int fn = 0; fn < 8; fn++) {
            rmax0 = fmaxf(rmax0, fmaxf(s[fn][0], s[fn][1]));
            rmax1 = fmaxf(rmax1, fmaxf(s[fn][2], s[fn][3]));
        }
        rmax0 = fmaxf(rmax0, __shfl_xor_sync(0xffffffffu, rmax0, 1));
        rmax0 = fmaxf(rmax0, __shfl_xor_sync(0xffffffffu, rmax0, 2));
        rmax1 = fmaxf(rmax1, __shfl_xor_sync(0xffffffffu, rmax1, 1));
        rmax1 = fmaxf(rmax1, __shfl_xor_sync(0xffffffffu, rmax1, 2));
        const float mn0 = fmaxf(m0, rmax0 * SCALE);
        const float mn1 = fmaxf(m1, rmax1 * SCALE);
        const float corr0 = __expf(m0 - mn0);
        const float corr1 = __expf(m1 - mn1);
        float sum0 = 0.f, sum1 = 0.f;
#pragma unroll
        for (int fn = 0; fn < 8; fn++) {
            s[fn][0] = __expf(fmaf(s[fn][0], SCALE, -mn0));
            s[fn][1] = __expf(fmaf(s[fn][1], SCALE, -mn0));
            s[fn][2] = __expf(fmaf(s[fn][2], SCALE, -mn1));
            s[fn][3] = __expf(fmaf(s[fn][3], SCALE, -mn1));
            sum0 += s[fn][0] + s[fn][1];
            sum1 += s[fn][2] + s[fn][3];
        }
        sum0 += __shfl_xor_sync(0xffffffffu, sum0, 1);
        sum0 += __shfl_xor_sync(0xffffffffu, sum0, 2);
        sum1 += __shfl_xor_sync(0xffffffffu, sum1, 1);
        sum1 += __shfl_xor_sync(0xffffffffu, sum1, 2);
        l0 = l0 * corr0 + sum0; m0 = mn0;
        l1 = l1 * corr1 + sum1; m1 = mn1;

#pragma unroll
        for (int fd = 0; fd < 16; fd++) {
            o[fd][0] *= corr0; o[fd][1] *= corr0;
            o[fd][2] *= corr1; o[fd][3] *= corr1;
        }

        uint32_t ph[4][4], pl[4][4];
#pragma unroll
        for (int ks2 = 0; ks2 < 4; ks2++) {
            const int j0 = 2 * ks2, j1 = j0 + 1;
            pack_hilo(s[j0][0], s[j0][1], ph[ks2][0], pl[ks2][0]);
            pack_hilo(s[j0][2], s[j0][3], ph[ks2][1], pl[ks2][1]);
            pack_hilo(s[j1][0], s[j1][1], ph[ks2][2], pl[ks2][2]);
            pack_hilo(s[j1][2], s[j1][3], ph[ks2][3], pl[ks2][3]);
        }

        if (bi + 1 < nblk) CP_WAIT1(); else CP_WAIT0();
        __syncthreads();

        // PV: O += (Ph+Pl) * Vh
#pragma unroll
        for (int ks2 = 0; ks2 < 4; ks2++) {
#pragma unroll
            for (int fd = 0; fd < 16; fd += 2) {
                const int vr = ks2 * 16 + (bTile & 1) * 8 + (lane & 7);
                const int vc = fd + (bTile >> 1);
                uint32_t vh4[4];
                LDSM_X4_T(vh4[0], vh4[1], vh4[2], vh4[3], VH + SA(vr, vc));
                mma16816(o[fd],     ph[ks2], vh4 + 0);
                mma16816(o[fd],     pl[ks2], vh4 + 0);
                mma16816(o[fd + 1], ph[ks2], vh4 + 2);
                mma16816(o[fd + 1], pl[ks2], vh4 + 2);
            }
        }
    }

    // epilogue: O /= l, write hi plane only (out GEMM is 2-term on O)
    const float inv0 = 1.f / l0;
    const float inv1 = 1.f / l1;
    const int er = lane >> 2;
    const int ec = (lane & 3) * 2;
    const size_t row0 = (size_t)(qb * 64 + w * 16 + er) * HID;
    const size_t row1 = row0 + (size_t)8 * HID;
#pragma unroll
    for (int fd = 0; fd < 16; fd++) {
        const int col = h * HD + fd * 8 + ec;
        __half2 h0 = __floats2half2_rn(o[fd][0] * inv0, o[fd][1] * inv0);
        __half2 h1 = __floats2half2_rn(o[fd][2] * inv1, o[fd][3] * inv1);
        *reinterpret_cast<uint32_t*>(g_oh + row0 + col) = h2bits(h0);
        *reinterpret_cast<uint32_t*>(g_oh + row1 + col) = h2bits(h1);
    }
}

// ---------------- launch -----------------------------------------------------
extern "C" void kernel_launch(void* const* d_in, const int* in_sizes, int n_in,
                              void* d_out, int out_size)
{
    const float* x    = (const float*)d_in[0];
    const int*   ridx = (const int*)d_in[1];
    const float* Wq   = (const float*)d_in[2];
    const float* Wk   = (const float*)d_in[3];
    const float* Wv   = (const float*)d_in[4];
    const float* Wo   = (const float*)d_in[5];
    float* out = (float*)d_out;

    cudaFuncSetAttribute(gemm_qkv, cudaFuncAttributeMaxDynamicSharedMemorySize, GEMM_SMEM);
    cudaFuncSetAttribute(gemm_out, cudaFuncAttributeMaxDynamicSharedMemorySize, GEMM_SMEM);
    cudaFuncSetAttribute(attn_mma, cudaFuncAttributeMaxDynamicSharedMemorySize, ATTN_SMEM);

    split_all<<<dim3(4096, 6), 256>>>(x, Wq, Wk, Wv, Wo);

    gemm_qkv<<<dim3(GN / 64, GM / 128, 3), 256, GEMM_SMEM>>>();

    attn_mma<<<dim3(NB, HEADS), 128, ATTN_SMEM>>>(ridx);

    gemm_out<<<dim3(GN / 64, GM / 128, 1), 256, GEMM_SMEM>>>(out);
}

// round 16
// speedup vs baseline: 2.1788x; 1.1725x over previous
#include <cuda_runtime.h>
#include <cuda_fp16.h>
#include <cstdint>
#include <cstddef>

#define SEQ    4096
#define HID    2048
#define HEADS  16
#define HD     128
#define NB     64
#define SCALE  0.08838834764831845f   // 1/sqrt(128)

#define GM 4096
#define GN 2048
#define GK 2048

// ---------------- scratch planes (device globals; no allocation allowed) ----
__device__ __half g_ah[SEQ * HID];                    // activations (hi only)
__device__ __half g_qh[SEQ * HID], g_ql[SEQ * HID];
__device__ __half g_kh[SEQ * HID], g_kl[SEQ * HID];
__device__ __half g_vh[SEQ * HID];
__device__ __half g_oh[SEQ * HID];                    // attn output (hi only)
__device__ __half g_wqh[HID * HID], g_wql[HID * HID];
__device__ __half g_wkh[HID * HID], g_wkl[HID * HID];
__device__ __half g_wvh[HID * HID];
__device__ __half g_woh[HID * HID];

// =================== baseline-PTX helpers (sm_80+ ISA only) =================
__device__ __forceinline__ uint32_t smem_u32(const void* p) {
    uint32_t a;
    asm("{ .reg .u64 t; cvta.to.shared.u64 t, %1; cvt.u32.u64 %0, t; }" : "=r"(a) : "l"(p));
    return a;
}
__device__ __forceinline__ void cpasync16(uint32_t dst, const void* src) {
    asm volatile("cp.async.cg.shared.global [%0], [%1], 16;" :: "r"(dst), "l"(src));
}
#define CP_COMMIT() asm volatile("cp.async.commit_group;" ::: "memory")
#define CP_WAIT1()  asm volatile("cp.async.wait_group 1;" ::: "memory")
#define CP_WAIT0()  asm volatile("cp.async.wait_group 0;" ::: "memory")

#define LDSM_X4(r0, r1, r2, r3, addr) \
    asm volatile("ldmatrix.sync.aligned.m8n8.x4.shared.b16 {%0,%1,%2,%3}, [%4];" \
                 : "=r"(r0), "=r"(r1), "=r"(r2), "=r"(r3) : "r"(addr))
#define LDSM_X4_T(r0, r1, r2, r3, addr) \
    asm volatile("ldmatrix.sync.aligned.m8n8.x4.trans.shared.b16 {%0,%1,%2,%3}, [%4];" \
                 : "=r"(r0), "=r"(r1), "=r"(r2), "=r"(r3) : "r"(addr))

__device__ __forceinline__ void mma16816(float* d, const uint32_t* a, const uint32_t* b) {
    asm volatile("mma.sync.aligned.m16n8k16.row.col.f32.f16.f16.f32 "
                 "{%0,%1,%2,%3}, {%4,%5,%6,%7}, {%8,%9}, {%0,%1,%2,%3};"
                 : "+f"(d[0]), "+f"(d[1]), "+f"(d[2]), "+f"(d[3])
                 : "r"(a[0]), "r"(a[1]), "r"(a[2]), "r"(a[3]), "r"(b[0]), "r"(b[1]));
}

__device__ __forceinline__ uint32_t h2bits(__half2 v) {
    return *reinterpret_cast<uint32_t*>(&v);
}
__device__ __forceinline__ void pack_hilo(float x, float y, uint32_t& hi, uint32_t& lo) {
    __half2 h = __floats2half2_rn(x, y);
    float2 f = __half22float2(h);
    __half2 l = __floats2half2_rn(x - f.x, y - f.y);
    hi = h2bits(h); lo = h2bits(l);
}

// =================== fused fp32 -> fp16 hi/lo split ==========================
// lo planes only for Wq, Wk (the softmax-sensitive paths).
#define REG4 (1u << 20)

__global__ __launch_bounds__(256) void split_all(
    const float* __restrict__ x,  const float* __restrict__ wq,
    const float* __restrict__ wk, const float* __restrict__ wv,
    const float* __restrict__ wo)
{
    const int r = blockIdx.y;
    const float* src;
    __half *hi, *lo = nullptr;
    size_t off = 0;
    if (r < 2)       { src = x;  hi = g_ah;               off = (size_t)r * REG4; }
    else if (r == 2) { src = wq; hi = g_wqh; lo = g_wql; }
    else if (r == 3) { src = wk; hi = g_wkh; lo = g_wkl; }
    else if (r == 4) { src = wv; hi = g_wvh; }
    else             { src = wo; hi = g_woh; }

    const size_t i = off + (size_t)blockIdx.x * 256 + threadIdx.x;
    float4 v = reinterpret_cast<const float4*>(src)[i];
    uint32_t h01, l01, h23, l23;
    pack_hilo(v.x, v.y, h01, l01);
    pack_hilo(v.z, v.w, h23, l23);
    reinterpret_cast<uint2*>(hi)[i] = make_uint2(h01, h23);
    if (lo)
        reinterpret_cast<uint2*>(lo)[i] = make_uint2(l01, l23);
}

// =================== fp16 GEMM core (mma.sync, 128x64, 3 CTA/SM) ============
// Proven geometry: warp tile 32x32 (4m x 2n warps), 2-stage cp.async,
// single sync per k-tile, __launch_bounds__(256,3).
// TERMS=2: C = Ah*Bh + Ah*Bl   TERMS=1: C = Ah*Bh (pure fp16, linear paths)
#define KTILE 32
#define NT (GK / KTILE)
#define ROWB 64
#define APLANE 8192                  // A: 128 rows * 64B
#define BPLANE 4096                  // B:  64 rows * 64B
#define STAGEB (APLANE + 2 * BPLANE)       // 16 KB (Ah, Bh, Bl)
#define GEMM_SMEM (2 * STAGEB)             // 32 KB
#define SWZ(r, c) ((uint32_t)((r) * ROWB + (((c) ^ (((r) >> 1) & 3)) * 16)))

template<int TERMS, bool SPLIT_OUT>
__device__ __forceinline__ void gemm_core(
    const __half* __restrict__ Ah,
    const __half* __restrict__ Bh, const __half* __restrict__ Bl,
    float* __restrict__ C, __half* __restrict__ Ch, __half* __restrict__ Cl)
{
    extern __shared__ char smem[];
    const uint32_t sb = smem_u32(smem);
    const int tid  = threadIdx.x;
    const int lane = tid & 31;
    const int w    = tid >> 5;
    const int bm   = blockIdx.y * 128;
    const int bn   = blockIdx.x * 64;

    const int lr  = tid >> 1;
    const int lc0 = (tid & 1) << 1;
    const __half* gAh = Ah + (size_t)(bm + lr) * GK + lc0 * 8;
    const uint32_t sA0 = SWZ(lr, lc0), sA1 = SWZ(lr, lc0 + 1);
    const int rb = tid >> 2;
    const int cb = tid & 3;
    const __half* gBh = Bh + (size_t)(bn + rb) * GK + cb * 8;
    const __half* gBl = (TERMS == 2) ? Bl + (size_t)(bn + rb) * GK + cb * 8 : nullptr;
    const uint32_t sB = SWZ(rb, cb);

    auto load_stage = [&](int t, int st) {
        const uint32_t base = sb + st * STAGEB;
        const int ko = t * KTILE;
        cpasync16(base + sA0, gAh + ko);
        cpasync16(base + sA1, gAh + ko + 8);
        cpasync16(base + APLANE + sB, gBh + ko);
        if (TERMS == 2)
            cpasync16(base + APLANE + BPLANE + sB, gBl + ko);
    };

    const int m0 = (w & 3) * 32;     // 4 warps over M
    const int n0 = (w >> 2) * 32;    // 2 warps over N

    const int xrA = ((lane >> 3) & 1) * 8 + (lane & 7);
    const int xcA = (lane >> 4) & 1;
    const int xrB = ((lane >> 4) & 1) * 8 + (lane & 7);
    const int xcB = (lane >> 3) & 1;

    float acc[8][4];
#pragma unroll
    for (int i = 0; i < 8; i++)
#pragma unroll
        for (int j = 0; j < 4; j++) acc[i][j] = 0.f;

    load_stage(0, 0);
    CP_COMMIT();

    for (int t = 0; t < NT; t++) {
        CP_WAIT0();
        __syncthreads();

        if (t + 1 < NT) {
            load_stage(t + 1, (t + 1) & 1);
            CP_COMMIT();
        }

        const uint32_t stage = sb + (t & 1) * STAGEB;
#pragma unroll
        for (int ks = 0; ks < 2; ks++) {
            uint32_t ah4[2][4];
#pragma unroll
            for (int fm = 0; fm < 2; fm++) {
                const uint32_t sw = SWZ(m0 + fm * 16 + xrA, 2 * ks + xcA);
                LDSM_X4(ah4[fm][0], ah4[fm][1], ah4[fm][2], ah4[fm][3], stage + sw);
            }
            uint32_t bh4[2][4], bl4[2][4];
#pragma unroll
            for (int fnp = 0; fnp < 2; fnp++) {
                const uint32_t sw = SWZ(n0 + fnp * 16 + xrB, 2 * ks + xcB);
                LDSM_X4(bh4[fnp][0], bh4[fnp][1], bh4[fnp][2], bh4[fnp][3],
                        stage + APLANE + sw);
                if (TERMS == 2)
                    LDSM_X4(bl4[fnp][0], bl4[fnp][1], bl4[fnp][2], bl4[fnp][3],
                            stage + APLANE + BPLANE + sw);
            }
            // combo 1: Ah * Bh
#pragma unroll
            for (int fm = 0; fm < 2; fm++)
#pragma unroll
                for (int fnp = 0; fnp < 2; fnp++) {
                    mma16816(acc[fm * 4 + 2 * fnp],     ah4[fm], bh4[fnp] + 0);
                    mma16816(acc[fm * 4 + 2 * fnp + 1], ah4[fm], bh4[fnp] + 2);
                }
            // combo 2: Ah * Bl
            if (TERMS == 2) {
#pragma unroll
                for (int fm = 0; fm < 2; fm++)
#pragma unroll
                    for (int fnp = 0; fnp < 2; fnp++) {
                        mma16816(acc[fm * 4 + 2 * fnp],     ah4[fm], bl4[fnp] + 0);
                        mma16816(acc[fm * 4 + 2 * fnp + 1], ah4[fm], bl4[fnp] + 2);
                    }
            }
        }
    }

    const int er = lane >> 2;
    const int ec = (lane & 3) * 2;
#pragma unroll
    for (int fm = 0; fm < 2; fm++) {
#pragma unroll
        for (int fn = 0; fn < 4; fn++) {
            const size_t r0 = (size_t)(bm + m0 + fm * 16 + er) * GN + bn + n0 + fn * 8 + ec;
            const size_t r1 = r0 + (size_t)8 * GN;
            float* ac = acc[fm * 4 + fn];
            if (SPLIT_OUT) {
                uint32_t h0, l0, h1, l1;
                pack_hilo(ac[0], ac[1], h0, l0);
                pack_hilo(ac[2], ac[3], h1, l1);
                *reinterpret_cast<uint32_t*>(Ch + r0) = h0;
                if (Cl) *reinterpret_cast<uint32_t*>(Cl + r0) = l0;
                *reinterpret_cast<uint32_t*>(Ch + r1) = h1;
                if (Cl) *reinterpret_cast<uint32_t*>(Cl + r1) = l1;
            } else {
                *reinterpret_cast<float2*>(C + r0) = make_float2(ac[0], ac[1]);
                *reinterpret_cast<float2*>(C + r1) = make_float2(ac[2], ac[3]);
            }
        }
    }
}

// Q,K: 2-term (softmax-sensitive); V: single-term fp16 (linear path)
__global__ __launch_bounds__(256, 3) void gemm_qkv()
{
    const int z = blockIdx.z;
    if (z == 0)
        gemm_core<2, true>(g_ah, g_wqh, g_wql, nullptr, g_qh, g_ql);
    else if (z == 1)
        gemm_core<2, true>(g_ah, g_wkh, g_wkl, nullptr, g_kh, g_kl);
    else
        gemm_core<1, true>(g_ah, g_wvh, nullptr, nullptr, g_vh, nullptr);
}

__global__ __launch_bounds__(256, 3) void gemm_out(float* __restrict__ C)
{
    gemm_core<1, false>(g_oh, g_woh, nullptr, C, nullptr, nullptr);
}

// =================== flash-style sparse attention (mma.sync, fp16) ==========
// S = (Qh+Ql)(Kh+Kl)^T 3-term; PV = (Ph+Pl)*Vh.
// Q fragments hoisted to registers; smem = Kh,Kl,Vh (48KB).
#define SA(r, c) ((uint32_t)((r) * 256 + (((c) ^ ((r) & 7)) * 16)))
#define ATTN_SMEM (3 * 16384)

__global__ __launch_bounds__(128, 2) void attn_mma(const int* __restrict__ rand_idx)
{
    extern __shared__ char smem[];
    const uint32_t sb = smem_u32(smem);
    const int tid  = threadIdx.x;
    const int lane = tid & 31;
    const int w    = tid >> 5;
    const int qb   = blockIdx.x;
    const int h    = blockIdx.y;

    int blist[6]; int nblk = 0;
    {
        int cand[6] = {qb, qb - 1, qb + 1, 0, NB - 1, rand_idx[qb]};
#pragma unroll
        for (int c = 0; c < 6; c++) {
            int b = cand[c];
            if (b < 0 || b >= NB) continue;
            bool dup = false;
            for (int d = 0; d < nblk; d++) dup |= (blist[d] == b);
            if (!dup) blist[nblk++] = b;
        }
    }

    const uint32_t KH = sb, KL = sb + 16384, VH = sb + 2 * 16384;

    auto load_pair = [&](uint32_t dh, uint32_t dl,
                         const __half* gh, const __half* gl, int j) {
        const __half* sh = gh + (size_t)(j * 64) * HID + h * HD;
        const __half* sl = gl + (size_t)(j * 64) * HID + h * HD;
#pragma unroll
        for (int t = 0; t < 8; t++) {
            int cid = tid + t * 128;
            int r = cid >> 4, c = cid & 15;
            cpasync16(dh + SA(r, c), sh + (size_t)r * HID + c * 8);
            cpasync16(dl + SA(r, c), sl + (size_t)r * HID + c * 8);
        }
    };
    auto load_one = [&](uint32_t dh, const __half* gh, int j) {
        const __half* sh = gh + (size_t)(j * 64) * HID + h * HD;
#pragma unroll
        for (int t = 0; t < 8; t++) {
            int cid = tid + t * 128;
            int r = cid >> 4, c = cid & 15;
            cpasync16(dh + SA(r, c), sh + (size_t)r * HID + c * 8);
        }
    };

    const int aRow  = w * 16 + (lane & 7) + ((lane >> 3) & 1) * 8;
    const int aCh   = (lane >> 4) & 1;
    const int bTile = lane >> 3;

    load_pair(KH, KL, g_qh, g_ql, qb);
    CP_COMMIT();
    CP_WAIT0();
    __syncthreads();
    uint32_t aqh[8][4], aql[8][4];
#pragma unroll
    for (int ks = 0; ks < 8; ks++) {
        LDSM_X4(aqh[ks][0], aqh[ks][1], aqh[ks][2], aqh[ks][3], KH + SA(aRow, 2 * ks + aCh));
        LDSM_X4(aql[ks][0], aql[ks][1], aql[ks][2], aql[ks][3], KL + SA(aRow, 2 * ks + aCh));
    }
    __syncthreads();

    load_pair(KH, KL, g_kh, g_kl, blist[0]);
    CP_COMMIT();

    float o[16][4];
#pragma unroll
    for (int i = 0; i < 16; i++)
#pragma unroll
        for (int j = 0; j < 4; j++) o[i][j] = 0.f;
    float m0 = -1e30f, m1 = -1e30f, l0 = 0.f, l1 = 0.f;

    for (int bi = 0; bi < nblk; bi++) {
        CP_WAIT0();
        __syncthreads();

        load_one(VH, g_vh, blist[bi]);
        CP_COMMIT();

        float s[8][4];
#pragma unroll
        for (int i = 0; i < 8; i++)
#pragma unroll
            for (int j = 0; j < 4; j++) s[i][j] = 0.f;

#pragma unroll
        for (int ks = 0; ks < 8; ks++) {
#pragma unroll
            for (int fn = 0; fn < 8; fn += 2) {
                const int br = (fn + (bTile >> 1)) * 8 + (lane & 7);
                const int bc = 2 * ks + (bTile & 1);
                uint32_t kh4[4], kl4[4];
                LDSM_X4(kh4[0], kh4[1], kh4[2], kh4[3], KH + SA(br, bc));
                LDSM_X4(kl4[0], kl4[1], kl4[2], kl4[3], KL + SA(br, bc));
                mma16816(s[fn],     aqh[ks], kh4 + 0);
                mma16816(s[fn],     aqh[ks], kl4 + 0);
                mma16816(s[fn],     aql[ks], kh4 + 0);
                mma16816(s[fn + 1], aqh[ks], kh4 + 2);
                mma16816(s[fn + 1], aqh[ks], kl4 + 2);
                mma16816(s[fn + 1], aql[ks], kh4 + 2);
            }
        }
        __syncthreads();

        if (bi + 1 < nblk) {
            load_pair(KH, KL, g_kh, g_kl, blist[bi + 1]);
            CP_COMMIT();
        }

        float rmax0 = -1e30f, rmax1 = -1e30f;
#pragma unroll
        for (int fn = 0; fn < 8; fn++) {
            rmax0 = fmaxf(rmax0, fmaxf(s[fn][0], s[fn][1]));
            rmax1 = fmaxf(rmax1, fmaxf(s[fn][2], s[fn][3]));
        }
        rmax0 = fmaxf(rmax0, __shfl_xor_sync(0xffffffffu, rmax0, 1));
        rmax0 = fmaxf(rmax0, __shfl_xor_sync(0xffffffffu, rmax0, 2));
        rmax1 = fmaxf(rmax1, __shfl_xor_sync(0xffffffffu, rmax1, 1));
        rmax1 = fmaxf(rmax1, __shfl_xor_sync(0xffffffffu, rmax1, 2));
        const float mn0 = fmaxf(m0, rmax0 * SCALE);
        const float mn1 = fmaxf(m1, rmax1 * SCALE);
        const float corr0 = __expf(m0 - mn0);
        const float corr1 = __expf(m1 - mn1);
        float sum0 = 0.f, sum1 = 0.f;
#pragma unroll
        for (int fn = 0; fn < 8; fn++) {
            s[fn][0] = __expf(fmaf(s[fn][0], SCALE, -mn0));
            s[fn][1] = __expf(fmaf(s[fn][1], SCALE, -mn0));
            s[fn][2] = __expf(fmaf(s[fn][2], SCALE, -mn1));
            s[fn][3] = __expf(fmaf(s[fn][3], SCALE, -mn1));
            sum0 += s[fn][0] + s[fn][1];
            sum1 += s[fn][2] + s[fn][3];
        }
        sum0 += __shfl_xor_sync(0xffffffffu, sum0, 1);
        sum0 += __shfl_xor_sync(0xffffffffu, sum0, 2);
        sum1 += __shfl_xor_sync(0xffffffffu, sum1, 1);
        sum1 += __shfl_xor_sync(0xffffffffu, sum1, 2);
        l0 = l0 * corr0 + sum0; m0 = mn0;
        l1 = l1 * corr1 + sum1; m1 = mn1;

#pragma unroll
        for (int fd = 0; fd < 16; fd++) {
            o[fd][0] *= corr0; o[fd][1] *= corr0;
            o[fd][2] *= corr1; o[fd][3] *= corr1;
        }

        uint32_t ph[4][4], pl[4][4];
#pragma unroll
        for (int ks2 = 0; ks2 < 4; ks2++) {
            const int j0 = 2 * ks2, j1 = j0 + 1;
            pack_hilo(s[j0][0], s[j0][1], ph[ks2][0], pl[ks2][0]);
            pack_hilo(s[j0][2], s[j0][3], ph[ks2][1], pl[ks2][1]);
            pack_hilo(s[j1][0], s[j1][1], ph[ks2][2], pl[ks2][2]);
            pack_hilo(s[j1][2], s[j1][3], ph[ks2][3], pl[ks2][3]);
        }

        if (bi + 1 < nblk) CP_WAIT1(); else CP_WAIT0();
        __syncthreads();

        // PV: O += (Ph+Pl) * Vh
#pragma unroll
        for (int ks2 = 0; ks2 < 4; ks2++) {
#pragma unroll
            for (int fd = 0; fd < 16; fd += 2) {
                const int vr = ks2 * 16 + (bTile & 1) * 8 + (lane & 7);
                const int vc = fd + (bTile >> 1);
                uint32_t vh4[4];
                LDSM_X4_T(vh4[0], vh4[1], vh4[2], vh4[3], VH + SA(vr, vc));
                mma16816(o[fd],     ph[ks2], vh4 + 0);
                mma16816(o[fd],     pl[ks2], vh4 + 0);
                mma16816(o[fd + 1], ph[ks2], vh4 + 2);
                mma16816(o[fd + 1], pl[ks2], vh4 + 2);
            }
        }
    }

    const float inv0 = 1.f / l0;
    const float inv1 = 1.f / l1;
    const int er = lane >> 2;
    const int ec = (lane & 3) * 2;
    const size_t row0 = (size_t)(qb * 64 + w * 16 + er) * HID;
    const size_t row1 = row0 + (size_t)8 * HID;
#pragma unroll
    for (int fd = 0; fd < 16; fd++) {
        const int col = h * HD + fd * 8 + ec;
        __half2 h0 = __floats2half2_rn(o[fd][0] * inv0, o[fd][1] * inv0);
        __half2 h1 = __floats2half2_rn(o[fd][2] * inv1, o[fd][3] * inv1);
        *reinterpret_cast<uint32_t*>(g_oh + row0 + col) = h2bits(h0);
        *reinterpret_cast<uint32_t*>(g_oh + row1 + col) = h2bits(h1);
    }
}

// ---------------- launch -----------------------------------------------------
extern "C" void kernel_launch(void* const* d_in, const int* in_sizes, int n_in,
                              void* d_out, int out_size)
{
    const float* x    = (const float*)d_in[0];
    const int*   ridx = (const int*)d_in[1];
    const float* Wq   = (const float*)d_in[2];
    const float* Wk   = (const float*)d_in[3];
    const float* Wv   = (const float*)d_in[4];
    const float* Wo   = (const float*)d_in[5];
    float* out = (float*)d_out;

    cudaFuncSetAttribute(gemm_qkv, cudaFuncAttributeMaxDynamicSharedMemorySize, GEMM_SMEM);
    cudaFuncSetAttribute(gemm_out, cudaFuncAttributeMaxDynamicSharedMemorySize, GEMM_SMEM);
    cudaFuncSetAttribute(attn_mma, cudaFuncAttributeMaxDynamicSharedMemorySize, ATTN_SMEM);

    split_all<<<dim3(4096, 6), 256>>>(x, Wq, Wk, Wv, Wo);

    gemm_qkv<<<dim3(GN / 64, GM / 128, 3), 256, GEMM_SMEM>>>();

    attn_mma<<<dim3(NB, HEADS), 128, ATTN_SMEM>>>(ridx);

    gemm_out<<<dim3(GN / 64, GM / 128, 1), 256, GEMM_SMEM>>>(out);
}

// round 17
// speedup vs baseline: 2.5630x; 1.1763x over previous
#include <cuda_runtime.h>
#include <cuda_fp16.h>
#include <cstdint>
#include <cstddef>

#define SEQ    4096
#define HID    2048
#define HEADS  16
#define HD     128
#define NB     64
#define SCALE  0.08838834764831845f   // 1/sqrt(128)

#define GM 4096
#define GN 2048
#define GK 2048

// ---------------- scratch planes (device globals; no allocation allowed) ----
__device__ __half g_ah[SEQ * HID];                    // activations (hi only)
__device__ __half g_qh[SEQ * HID], g_ql[SEQ * HID];   // q hi+lo (storage comp)
__device__ __half g_kh[SEQ * HID], g_kl[SEQ * HID];   // k hi+lo (storage comp)
__device__ __half g_vh[SEQ * HID];
__device__ __half g_oh[SEQ * HID];                    // attn output (hi only)
__device__ __half g_wqh[HID * HID];
__device__ __half g_wkh[HID * HID];
__device__ __half g_wvh[HID * HID];
__device__ __half g_woh[HID * HID];

// =================== baseline-PTX helpers (sm_80+ ISA only) =================
__device__ __forceinline__ uint32_t smem_u32(const void* p) {
    uint32_t a;
    asm("{ .reg .u64 t; cvta.to.shared.u64 t, %1; cvt.u32.u64 %0, t; }" : "=r"(a) : "l"(p));
    return a;
}
__device__ __forceinline__ void cpasync16(uint32_t dst, const void* src) {
    asm volatile("cp.async.cg.shared.global [%0], [%1], 16;" :: "r"(dst), "l"(src));
}
#define CP_COMMIT() asm volatile("cp.async.commit_group;" ::: "memory")
#define CP_WAIT1()  asm volatile("cp.async.wait_group 1;" ::: "memory")
#define CP_WAIT0()  asm volatile("cp.async.wait_group 0;" ::: "memory")

#define LDSM_X4(r0, r1, r2, r3, addr) \
    asm volatile("ldmatrix.sync.aligned.m8n8.x4.shared.b16 {%0,%1,%2,%3}, [%4];" \
                 : "=r"(r0), "=r"(r1), "=r"(r2), "=r"(r3) : "r"(addr))
#define LDSM_X4_T(r0, r1, r2, r3, addr) \
    asm volatile("ldmatrix.sync.aligned.m8n8.x4.trans.shared.b16 {%0,%1,%2,%3}, [%4];" \
                 : "=r"(r0), "=r"(r1), "=r"(r2), "=r"(r3) : "r"(addr))

__device__ __forceinline__ void mma16816(float* d, const uint32_t* a, const uint32_t* b) {
    asm volatile("mma.sync.aligned.m16n8k16.row.col.f32.f16.f16.f32 "
                 "{%0,%1,%2,%3}, {%4,%5,%6,%7}, {%8,%9}, {%0,%1,%2,%3};"
                 : "+f"(d[0]), "+f"(d[1]), "+f"(d[2]), "+f"(d[3])
                 : "r"(a[0]), "r"(a[1]), "r"(a[2]), "r"(a[3]), "r"(b[0]), "r"(b[1]));
}

__device__ __forceinline__ uint32_t h2bits(__half2 v) {
    return *reinterpret_cast<uint32_t*>(&v);
}
__device__ __forceinline__ void pack_hilo(float x, float y, uint32_t& hi, uint32_t& lo) {
    __half2 h = __floats2half2_rn(x, y);
    float2 f = __half22float2(h);
    __half2 l = __floats2half2_rn(x - f.x, y - f.y);
    hi = h2bits(h); lo = h2bits(l);
}

// =================== fused fp32 -> fp16 convert (hi only) ====================
#define REG4 (1u << 20)

__global__ __launch_bounds__(256) void split_all(
    const float* __restrict__ x,  const float* __restrict__ wq,
    const float* __restrict__ wk, const float* __restrict__ wv,
    const float* __restrict__ wo)
{
    const int r = blockIdx.y;
    const float* src;
    __half* hi;
    size_t off = 0;
    if (r < 2)       { src = x;  hi = g_ah;  off = (size_t)r * REG4; }
    else if (r == 2) { src = wq; hi = g_wqh; }
    else if (r == 3) { src = wk; hi = g_wkh; }
    else if (r == 4) { src = wv; hi = g_wvh; }
    else             { src = wo; hi = g_woh; }

    const size_t i = off + (size_t)blockIdx.x * 256 + threadIdx.x;
    float4 v = reinterpret_cast<const float4*>(src)[i];
    __half2 h01 = __floats2half2_rn(v.x, v.y);
    __half2 h23 = __floats2half2_rn(v.z, v.w);
    reinterpret_cast<uint2*>(hi)[i] = make_uint2(h2bits(h01), h2bits(h23));
}

// =================== fp16 GEMM core (mma.sync, 128x64, 3 CTA/SM) ============
// Single-term pure fp16: C = Ah*Bh, fp32 accumulate.
// Proven geometry: warp tile 32x32 (4m x 2n warps), 2-stage cp.async,
// single sync per k-tile, __launch_bounds__(256,3).
#define KTILE 32
#define NT (GK / KTILE)
#define ROWB 64
#define APLANE 8192                  // A: 128 rows * 64B
#define BPLANE 4096                  // B:  64 rows * 64B
#define STAGEB (APLANE + BPLANE)           // 12 KB (Ah, Bh)
#define GEMM_SMEM (2 * STAGEB)             // 24 KB
#define SWZ(r, c) ((uint32_t)((r) * ROWB + (((c) ^ (((r) >> 1) & 3)) * 16)))

template<bool SPLIT_OUT>
__device__ __forceinline__ void gemm_core(
    const __half* __restrict__ Ah, const __half* __restrict__ Bh,
    float* __restrict__ C, __half* __restrict__ Ch, __half* __restrict__ Cl)
{
    extern __shared__ char smem[];
    const uint32_t sb = smem_u32(smem);
    const int tid  = threadIdx.x;
    const int lane = tid & 31;
    const int w    = tid >> 5;
    const int bm   = blockIdx.y * 128;
    const int bn   = blockIdx.x * 64;

    const int lr  = tid >> 1;
    const int lc0 = (tid & 1) << 1;
    const __half* gAh = Ah + (size_t)(bm + lr) * GK + lc0 * 8;
    const uint32_t sA0 = SWZ(lr, lc0), sA1 = SWZ(lr, lc0 + 1);
    const int rb = tid >> 2;
    const int cb = tid & 3;
    const __half* gBh = Bh + (size_t)(bn + rb) * GK + cb * 8;
    const uint32_t sB = SWZ(rb, cb);

    auto load_stage = [&](int t, int st) {
        const uint32_t base = sb + st * STAGEB;
        const int ko = t * KTILE;
        cpasync16(base + sA0, gAh + ko);
        cpasync16(base + sA1, gAh + ko + 8);
        cpasync16(base + APLANE + sB, gBh + ko);
    };

    const int m0 = (w & 3) * 32;     // 4 warps over M
    const int n0 = (w >> 2) * 32;    // 2 warps over N

    const int xrA = ((lane >> 3) & 1) * 8 + (lane & 7);
    const int xcA = (lane >> 4) & 1;
    const int xrB = ((lane >> 4) & 1) * 8 + (lane & 7);
    const int xcB = (lane >> 3) & 1;

    float acc[8][4];
#pragma unroll
    for (int i = 0; i < 8; i++)
#pragma unroll
        for (int j = 0; j < 4; j++) acc[i][j] = 0.f;

    load_stage(0, 0);
    CP_COMMIT();

    for (int t = 0; t < NT; t++) {
        CP_WAIT0();
        __syncthreads();

        if (t + 1 < NT) {
            load_stage(t + 1, (t + 1) & 1);
            CP_COMMIT();
        }

        const uint32_t stage = sb + (t & 1) * STAGEB;
#pragma unroll
        for (int ks = 0; ks < 2; ks++) {
            uint32_t ah4[2][4];
#pragma unroll
            for (int fm = 0; fm < 2; fm++) {
                const uint32_t sw = SWZ(m0 + fm * 16 + xrA, 2 * ks + xcA);
                LDSM_X4(ah4[fm][0], ah4[fm][1], ah4[fm][2], ah4[fm][3], stage + sw);
            }
            uint32_t bh4[2][4];
#pragma unroll
            for (int fnp = 0; fnp < 2; fnp++) {
                const uint32_t sw = SWZ(n0 + fnp * 16 + xrB, 2 * ks + xcB);
                LDSM_X4(bh4[fnp][0], bh4[fnp][1], bh4[fnp][2], bh4[fnp][3],
                        stage + APLANE + sw);
            }
#pragma unroll
            for (int fm = 0; fm < 2; fm++)
#pragma unroll
                for (int fnp = 0; fnp < 2; fnp++) {
                    mma16816(acc[fm * 4 + 2 * fnp],     ah4[fm], bh4[fnp] + 0);
                    mma16816(acc[fm * 4 + 2 * fnp + 1], ah4[fm], bh4[fnp] + 2);
                }
        }
    }

    const int er = lane >> 2;
    const int ec = (lane & 3) * 2;
#pragma unroll
    for (int fm = 0; fm < 2; fm++) {
#pragma unroll
        for (int fn = 0; fn < 4; fn++) {
            const size_t r0 = (size_t)(bm + m0 + fm * 16 + er) * GN + bn + n0 + fn * 8 + ec;
            const size_t r1 = r0 + (size_t)8 * GN;
            float* ac = acc[fm * 4 + fn];
            if (SPLIT_OUT) {
                uint32_t h0, l0, h1, l1;
                pack_hilo(ac[0], ac[1], h0, l0);
                pack_hilo(ac[2], ac[3], h1, l1);
                *reinterpret_cast<uint32_t*>(Ch + r0) = h0;
                if (Cl) *reinterpret_cast<uint32_t*>(Cl + r0) = l0;
                *reinterpret_cast<uint32_t*>(Ch + r1) = h1;
                if (Cl) *reinterpret_cast<uint32_t*>(Cl + r1) = l1;
            } else {
                *reinterpret_cast<float2*>(C + r0) = make_float2(ac[0], ac[1]);
                *reinterpret_cast<float2*>(C + r1) = make_float2(ac[2], ac[3]);
            }
        }
    }
}

// All projections single-term fp16; Q,K store hi+lo (fp32 accum split),
// so attention's 3-term S fully compensates their storage rounding.
__global__ __launch_bounds__(256, 3) void gemm_qkv()
{
    const int z = blockIdx.z;
    if (z == 0)
        gemm_core<true>(g_ah, g_wqh, nullptr, g_qh, g_ql);
    else if (z == 1)
        gemm_core<true>(g_ah, g_wkh, nullptr, g_kh, g_kl);
    else
        gemm_core<true>(g_ah, g_wvh, nullptr, g_vh, nullptr);
}

__global__ __launch_bounds__(256, 3) void gemm_out(float* __restrict__ C)
{
    gemm_core<false>(g_oh, g_woh, C, nullptr, nullptr);
}

// =================== flash-style sparse attention (mma.sync, fp16) ==========
// S = (Qh+Ql)(Kh+Kl)^T 3-term; PV = (Ph+Pl)*Vh.
// Q fragments hoisted to registers; smem = Kh,Kl,Vh (48KB).
#define SA(r, c) ((uint32_t)((r) * 256 + (((c) ^ ((r) & 7)) * 16)))
#define ATTN_SMEM (3 * 16384)

__global__ __launch_bounds__(128, 2) void attn_mma(const int* __restrict__ rand_idx)
{
    extern __shared__ char smem[];
    const uint32_t sb = smem_u32(smem);
    const int tid  = threadIdx.x;
    const int lane = tid & 31;
    const int w    = tid >> 5;
    const int qb   = blockIdx.x;
    const int h    = blockIdx.y;

    int blist[6]; int nblk = 0;
    {
        int cand[6] = {qb, qb - 1, qb + 1, 0, NB - 1, rand_idx[qb]};
#pragma unroll
        for (int c = 0; c < 6; c++) {
            int b = cand[c];
            if (b < 0 || b >= NB) continue;
            bool dup = false;
            for (int d = 0; d < nblk; d++) dup |= (blist[d] == b);
            if (!dup) blist[nblk++] = b;
        }
    }

    const uint32_t KH = sb, KL = sb + 16384, VH = sb + 2 * 16384;

    auto load_pair = [&](uint32_t dh, uint32_t dl,
                         const __half* gh, const __half* gl, int j) {
        const __half* sh = gh + (size_t)(j * 64) * HID + h * HD;
        const __half* sl = gl + (size_t)(j * 64) * HID + h * HD;
#pragma unroll
        for (int t = 0; t < 8; t++) {
            int cid = tid + t * 128;
            int r = cid >> 4, c = cid & 15;
            cpasync16(dh + SA(r, c), sh + (size_t)r * HID + c * 8);
            cpasync16(dl + SA(r, c), sl + (size_t)r * HID + c * 8);
        }
    };
    auto load_one = [&](uint32_t dh, const __half* gh, int j) {
        const __half* sh = gh + (size_t)(j * 64) * HID + h * HD;
#pragma unroll
        for (int t = 0; t < 8; t++) {
            int cid = tid + t * 128;
            int r = cid >> 4, c = cid & 15;
            cpasync16(dh + SA(r, c), sh + (size_t)r * HID + c * 8);
        }
    };

    const int aRow  = w * 16 + (lane & 7) + ((lane >> 3) & 1) * 8;
    const int aCh   = (lane >> 4) & 1;
    const int bTile = lane >> 3;

    load_pair(KH, KL, g_qh, g_ql, qb);
    CP_COMMIT();
    CP_WAIT0();
    __syncthreads();
    uint32_t aqh[8][4], aql[8][4];
#pragma unroll
    for (int ks = 0; ks < 8; ks++) {
        LDSM_X4(aqh[ks][0], aqh[ks][1], aqh[ks][2], aqh[ks][3], KH + SA(aRow, 2 * ks + aCh));
        LDSM_X4(aql[ks][0], aql[ks][1], aql[ks][2], aql[ks][3], KL + SA(aRow, 2 * ks + aCh));
    }
    __syncthreads();

    load_pair(KH, KL, g_kh, g_kl, blist[0]);
    CP_COMMIT();

    float o[16][4];
#pragma unroll
    for (int i = 0; i < 16; i++)
#pragma unroll
        for (int j = 0; j < 4; j++) o[i][j] = 0.f;
    float m0 = -1e30f, m1 = -1e30f, l0 = 0.f, l1 = 0.f;

    for (int bi = 0; bi < nblk; bi++) {
        CP_WAIT0();
        __syncthreads();

        load_one(VH, g_vh, blist[bi]);
        CP_COMMIT();

        float s[8][4];
#pragma unroll
        for (int i = 0; i < 8; i++)
#pragma unroll
            for (int j = 0; j < 4; j++) s[i][j] = 0.f;

#pragma unroll
        for (int ks = 0; ks < 8; ks++) {
#pragma unroll
            for (int fn = 0; fn < 8; fn += 2) {
                const int br = (fn + (bTile >> 1)) * 8 + (lane & 7);
                const int bc = 2 * ks + (bTile & 1);
                uint32_t kh4[4], kl4[4];
                LDSM_X4(kh4[0], kh4[1], kh4[2], kh4[3], KH + SA(br, bc));
                LDSM_X4(kl4[0], kl4[1], kl4[2], kl4[3], KL + SA(br, bc));
                mma16816(s[fn],     aqh[ks], kh4 + 0);
                mma16816(s[fn],     aqh[ks], kl4 + 0);
                mma16816(s[fn],     aql[ks], kh4 + 0);
                mma16816(s[fn + 1], aqh[ks], kh4 + 2);
                mma16816(s[fn + 1], aqh[ks], kl4 + 2);
                mma16816(s[fn + 1], aql[ks], kh4 + 2);
            }
        }
        __syncthreads();

        if (bi + 1 < nblk) {
            load_pair(KH, KL, g_kh, g_kl, blist[bi + 1]);
            CP_COMMIT();
        }

        float rmax0 = -1e30f, rmax1 = -1e30f;
#pragma unroll
        for (int fn = 0; fn < 8; fn++) {
            rmax0 = fmaxf(rmax0, fmaxf(s[fn][0], s[fn][1]));
            rmax1 = fmaxf(rmax1, fmaxf(s[fn][2], s[fn][3]));
        }
        rmax0 = fmaxf(rmax0, __shfl_xor_sync(0xffffffffu, rmax0, 1));
        rmax0 = fmaxf(rmax0, __shfl_xor_sync(0xffffffffu, rmax0, 2));
        rmax1 = fmaxf(rmax1, __shfl_xor_sync(0xffffffffu, rmax1, 1));
        rmax1 = fmaxf(rmax1, __shfl_xor_sync(0xffffffffu, rmax1, 2));
        const float mn0 = fmaxf(m0, rmax0 * SCALE);
        const float mn1 = fmaxf(m1, rmax1 * SCALE);
        const float corr0 = __expf(m0 - mn0);
        const float corr1 = __expf(m1 - mn1);
        float sum0 = 0.f, sum1 = 0.f;
#pragma unroll
        for (int fn = 0; fn < 8; fn++) {
            s[fn][0] = __expf(fmaf(s[fn][0], SCALE, -mn0));
            s[fn][1] = __expf(fmaf(s[fn][1], SCALE, -mn0));
            s[fn][2] = __expf(fmaf(s[fn][2], SCALE, -mn1));
            s[fn][3] = __expf(fmaf(s[fn][3], SCALE, -mn1));
            sum0 += s[fn][0] + s[fn][1];
            sum1 += s[fn][2] + s[fn][3];
        }
        sum0 += __shfl_xor_sync(0xffffffffu, sum0, 1);
        sum0 += __shfl_xor_sync(0xffffffffu, sum0, 2);
        sum1 += __shfl_xor_sync(0xffffffffu, sum1, 1);
        sum1 += __shfl_xor_sync(0xffffffffu, sum1, 2);
        l0 = l0 * corr0 + sum0; m0 = mn0;
        l1 = l1 * corr1 + sum1; m1 = mn1;

#pragma unroll
        for (int fd = 0; fd < 16; fd++) {
            o[fd][0] *= corr0; o[fd][1] *= corr0;
            o[fd][2] *= corr1; o[fd][3] *= corr1;
        }

        uint32_t ph[4][4], pl[4][4];
#pragma unroll
        for (int ks2 = 0; ks2 < 4; ks2++) {
            const int j0 = 2 * ks2, j1 = j0 + 1;
            pack_hilo(s[j0][0], s[j0][1], ph[ks2][0], pl[ks2][0]);
            pack_hilo(s[j0][2], s[j0][3], ph[ks2][1], pl[ks2][1]);
            pack_hilo(s[j1][0], s[j1][1], ph[ks2][2], pl[ks2][2]);
            pack_hilo(s[j1][2], s[j1][3], ph[ks2][3], pl[ks2][3]);
        }

        if (bi + 1 < nblk) CP_WAIT1(); else CP_WAIT0();
        __syncthreads();

        // PV: O += (Ph+Pl) * Vh
#pragma unroll
        for (int ks2 = 0; ks2 < 4; ks2++) {
#pragma unroll
            for (int fd = 0; fd < 16; fd += 2) {
                const int vr = ks2 * 16 + (bTile & 1) * 8 + (lane & 7);
                const int vc = fd + (bTile >> 1);
                uint32_t vh4[4];
                LDSM_X4_T(vh4[0], vh4[1], vh4[2], vh4[3], VH + SA(vr, vc));
                mma16816(o[fd],     ph[ks2], vh4 + 0);
                mma16816(o[fd],     pl[ks2], vh4 + 0);
                mma16816(o[fd + 1], ph[ks2], vh4 + 2);
                mma16816(o[fd + 1], pl[ks2], vh4 + 2);
            }
        }
    }

    const float inv0 = 1.f / l0;
    const float inv1 = 1.f / l1;
    const int er = lane >> 2;
    const int ec = (lane & 3) * 2;
    const size_t row0 = (size_t)(qb * 64 + w * 16 + er) * HID;
    const size_t row1 = row0 + (size_t)8 * HID;
#pragma unroll
    for (int fd = 0; fd < 16; fd++) {
        const int col = h * HD + fd * 8 + ec;
        __half2 h0 = __floats2half2_rn(o[fd][0] * inv0, o[fd][1] * inv0);
        __half2 h1 = __floats2half2_rn(o[fd][2] * inv1, o[fd][3] * inv1);
        *reinterpret_cast<uint32_t*>(g_oh + row0 + col) = h2bits(h0);
        *reinterpret_cast<uint32_t*>(g_oh + row1 + col) = h2bits(h1);
    }
}

// ---------------- launch -----------------------------------------------------
extern "C" void kernel_launch(void* const* d_in, const int* in_sizes, int n_in,
                              void* d_out, int out_size)
{
    const float* x    = (const float*)d_in[0];
    const int*   ridx = (const int*)d_in[1];
    const float* Wq   = (const float*)d_in[2];
    const float* Wk   = (const float*)d_in[3];
    const float* Wv   = (const float*)d_in[4];
    const float* Wo   = (const float*)d_in[5];
    float* out = (float*)d_out;

    cudaFuncSetAttribute(gemm_qkv, cudaFuncAttributeMaxDynamicSharedMemorySize, GEMM_SMEM);
    cudaFuncSetAttribute(gemm_out, cudaFuncAttributeMaxDynamicSharedMemorySize, GEMM_SMEM);
    cudaFuncSetAttribute(attn_mma, cudaFuncAttributeMaxDynamicSharedMemorySize, ATTN_SMEM);

    split_all<<<dim3(4096, 6), 256>>>(x, Wq, Wk, Wv, Wo);

    gemm_qkv<<<dim3(GN / 64, GM / 128, 3), 256, GEMM_SMEM>>>();

    attn_mma<<<dim3(NB, HEADS), 128, ATTN_SMEM>>>(ridx);

    gemm_out<<<dim3(GN / 64, GM / 128, 1), 256, GEMM_SMEM>>>(out);
}